// round 8
// baseline (speedup 1.0000x reference)
#include <cuda_runtime.h>
#include <cuda_bf16.h>
#include <cstdint>

#define BB 2
#define SS 2048
#define DD 1024
#define HH 16
#define HDD 64
#define BHH 32
#define MTOT 4096
#define NQKV 3072

typedef __nv_bfloat16 bf16;
typedef __nv_bfloat162 bf162;

// split operands (__device__ globals: allocation-free rule), 16B aligned
__device__ __align__(16) bf16 g_xhi[MTOT*DD], g_xlo[MTOT*DD];
__device__ __align__(16) bf16 g_wqh[DD*NQKV], g_wql[DD*NQKV];   // W_qkv natural [k][n]
__device__ __align__(16) bf16 g_woh[DD*DD],   g_wol[DD*DD];     // W_out  natural [k][n]
__device__ __align__(16) bf16 g_qh[BHH*SS*HDD], g_ql[BHH*SS*HDD];  // [bh][s][hd]
__device__ __align__(16) bf16 g_kh[BHH*SS*HDD], g_kl[BHH*SS*HDD];
__device__ __align__(16) bf16 g_vh[BHH*SS*HDD], g_vl[BHH*SS*HDD];
__device__ __align__(16) bf16 g_aoh[MTOT*DD], g_aol[MTOT*DD];      // [b*s][d]

// ---------------- helpers ----------------
__device__ __forceinline__ uint32_t smem_u32(const void* p){
    uint32_t a;
    asm("{ .reg .u64 t; cvta.to.shared.u64 t, %1; cvt.u32.u64 %0, t; }":"=r"(a):"l"(p));
    return a;
}
__device__ __forceinline__ void cp16(uint32_t d, const void* s){
    asm volatile("cp.async.cg.shared.global [%0], [%1], 16;"::"r"(d),"l"(s));
}
__device__ __forceinline__ void cp_commit(){ asm volatile("cp.async.commit_group;":::"memory"); }
template<int N> __device__ __forceinline__ void cp_wait(){
    asm volatile("cp.async.wait_group %0;"::"n"(N):"memory");
}
__device__ __forceinline__ void ldsm4(uint32_t* r, uint32_t a){
    asm volatile("ldmatrix.sync.aligned.m8n8.x4.shared.b16 {%0,%1,%2,%3}, [%4];"
        :"=r"(r[0]),"=r"(r[1]),"=r"(r[2]),"=r"(r[3]):"r"(a));
}
__device__ __forceinline__ void ldsm4t(uint32_t* r, uint32_t a){
    asm volatile("ldmatrix.sync.aligned.m8n8.x4.trans.shared.b16 {%0,%1,%2,%3}, [%4];"
        :"=r"(r[0]),"=r"(r[1]),"=r"(r[2]),"=r"(r[3]):"r"(a));
}
__device__ __forceinline__ void mma_bf(float* c, const uint32_t* a, uint32_t b0, uint32_t b1){
    asm volatile("mma.sync.aligned.m16n8k16.row.col.f32.bf16.bf16.f32 "
        "{%0,%1,%2,%3}, {%4,%5,%6,%7}, {%8,%9}, {%0,%1,%2,%3};"
        :"+f"(c[0]),"+f"(c[1]),"+f"(c[2]),"+f"(c[3])
        :"r"(a[0]),"r"(a[1]),"r"(a[2]),"r"(a[3]),"r"(b0),"r"(b1));
}
__device__ __forceinline__ uint32_t packbf(float x, float y){
    bf162 t = __floats2bfloat162_rn(x, y);
    return *reinterpret_cast<uint32_t*>(&t);
}
__device__ __forceinline__ float bfhi(float v){
    return __bfloat162float(__float2bfloat16(v));
}
__device__ __forceinline__ float ex2(float x){
    float y; asm("ex2.approx.f32 %0, %1;":"=f"(y):"f"(x)); return y;
}

// ---------------- prep: fp32 -> (hi,lo) bf16 ----------------
template<int SEL>
__global__ __launch_bounds__(256)
void split_k(const float* __restrict__ src, int n4){
    bf16* hi = (SEL==0)? g_xhi : (SEL==1)? g_wqh : g_woh;
    bf16* lo = (SEL==0)? g_xlo : (SEL==1)? g_wql : g_wol;
    int i = blockIdx.x*256 + threadIdx.x;
    if (i < n4){
        float4 v = reinterpret_cast<const float4*>(src)[i];
        float hx=bfhi(v.x), hy=bfhi(v.y), hz=bfhi(v.z), hw=bfhi(v.w);
        reinterpret_cast<uint32_t*>(hi)[i*2+0] = packbf(hx,hy);
        reinterpret_cast<uint32_t*>(hi)[i*2+1] = packbf(hz,hw);
        reinterpret_cast<uint32_t*>(lo)[i*2+0] = packbf(v.x-hx, v.y-hy);
        reinterpret_cast<uint32_t*>(lo)[i*2+1] = packbf(v.z-hz, v.w-hw);
    }
}

// ---------------- split-bf16 GEMM: 128x128 CTA tile, 4 warps of 64x64 ----------
// A tile: 128 rows x (32hi|32lo|pad) bf16, row = 144B  -> 18432 B
// B tile:  32 k    x (128hi|128lo|pad) bf16, row = 528B -> 16896 B
#define GSTAGE 35328
#define GSMEM  (3*GSTAGE)

template<int MODE>
__global__ __launch_bounds__(128, 2)
void gemm_mma(const float* __restrict__ bias, float* __restrict__ Cout){
    extern __shared__ char smem[];
    const bf16* Ahi = (MODE==0)? g_xhi : g_aoh;
    const bf16* Alo = (MODE==0)? g_xlo : g_aol;
    const bf16* Bhi = (MODE==0)? g_wqh : g_woh;
    const bf16* Blo = (MODE==0)? g_wql : g_wol;
    const int N = (MODE==0)? NQKV : DD;

    const int bm = blockIdx.y*128, bn = blockIdx.x*128;
    const int tid = threadIdx.x, lane = tid&31, wid = tid>>5;
    const int wm = wid>>1, wn = wid&1;   // warp tile 64(M) x 64(N)
    uint32_t sb = smem_u32(smem);

    float acc[4][8][4];
    #pragma unroll
    for (int a=0;a<4;a++)
        #pragma unroll
        for (int b=0;b<8;b++)
            #pragma unroll
            for (int c=0;c<4;c++) acc[a][b][c]=0.f;

    auto load_stage = [&](int t, int s){
        uint32_t as  = sb + s*GSTAGE;
        uint32_t bs2 = as + 18432;
        int k0 = t*32;
        #pragma unroll
        for (int i=0;i<8;i++){
            int id = i*128 + tid;
            int row = id>>3, seg = id&7;
            const bf16* src = (seg<4)? (Ahi + (size_t)(bm+row)*DD + k0 + seg*8)
                                     : (Alo + (size_t)(bm+row)*DD + k0 + (seg-4)*8);
            cp16(as + row*144 + seg*16, src);
        }
        #pragma unroll
        for (int i=0;i<8;i++){
            int id = i*128 + tid;
            int row = id>>5, seg = id&31;
            const bf16* src = (seg<16)? (Bhi + (size_t)(k0+row)*N + bn + seg*8)
                                      : (Blo + (size_t)(k0+row)*N + bn + (seg-16)*8);
            cp16(bs2 + row*528 + seg*16, src);
        }
        cp_commit();
    };

    load_stage(0,0);
    load_stage(1,1);
    int sl = 0, sl2 = 2;
    for (int t=0; t<32; t++){
        if (t<31) cp_wait<1>(); else cp_wait<0>();
        __syncthreads();
        if (t+2 < 32) load_stage(t+2, sl2);

        uint32_t as  = sb + sl*GSTAGE;
        uint32_t bs2 = as + 18432;
        #pragma unroll
        for (int k16=0;k16<2;k16++){
            uint32_t ah[4][4], al[4][4];
            #pragma unroll
            for (int mf=0;mf<4;mf++){
                uint32_t ad = as + (uint32_t)(wm*64+mf*16+(lane&15))*144
                            + k16*32 + ((lane>>4)<<4);
                ldsm4(ah[mf], ad);
                ldsm4(al[mf], ad+64);
            }
            uint32_t bhf[8][2], blf[8][2];
            #pragma unroll
            for (int g=0;g<4;g++){
                uint32_t kk = (uint32_t)(k16*16 + (lane&15));
                uint32_t bd = bs2 + kk*528
                            + ((uint32_t)(wn*64 + g*16 + ((lane>>4)<<3))<<1);
                uint32_t t4[4];
                ldsm4t(t4, bd);
                bhf[g*2][0]=t4[0]; bhf[g*2][1]=t4[1];
                bhf[g*2+1][0]=t4[2]; bhf[g*2+1][1]=t4[3];
                ldsm4t(t4, bd+256);
                blf[g*2][0]=t4[0]; blf[g*2][1]=t4[1];
                blf[g*2+1][0]=t4[2]; blf[g*2+1][1]=t4[3];
            }
            // 32 independent accumulators per term pass
            #pragma unroll
            for (int mf=0;mf<4;mf++)
                #pragma unroll
                for (int nf=0;nf<8;nf++)
                    mma_bf(acc[mf][nf], ah[mf], bhf[nf][0], bhf[nf][1]);
            #pragma unroll
            for (int mf=0;mf<4;mf++)
                #pragma unroll
                for (int nf=0;nf<8;nf++)
                    mma_bf(acc[mf][nf], ah[mf], blf[nf][0], blf[nf][1]);
            #pragma unroll
            for (int mf=0;mf<4;mf++)
                #pragma unroll
                for (int nf=0;nf<8;nf++)
                    mma_bf(acc[mf][nf], al[mf], bhf[nf][0], bhf[nf][1]);
        }
        sl  = (sl ==2)? 0 : sl+1;
        sl2 = (sl2==2)? 0 : sl2+1;
    }

    // epilogue
    #pragma unroll
    for (int mf=0;mf<4;mf++){
        #pragma unroll
        for (int nf=0;nf<8;nf++){
            int n0 = bn + wn*64 + nf*8 + ((lane&3)<<1);
            float b0v = bias[n0], b1v = bias[n0+1];
            #pragma unroll
            for (int hf=0; hf<2; hf++){
                int m = bm + wm*64 + mf*16 + (lane>>2) + hf*8;
                float v0 = acc[mf][nf][hf*2+0] + b0v;
                float v1 = acc[mf][nf][hf*2+1] + b1v;
                if (MODE==0){
                    int b = m>>11, s = m&(SS-1);
                    int h = n0/192, r = n0 - h*192;
                    float h0 = bfhi(v0), h1 = bfhi(v1);
                    uint32_t ph = packbf(h0,h1), pl = packbf(v0-h0, v1-h1);
                    size_t base = ((size_t)(b*HH+h)*SS + s)*HDD;
                    if (r < 64){
                        *(uint32_t*)(g_qh+base+r) = ph;
                        *(uint32_t*)(g_ql+base+r) = pl;
                    } else if (r < 128){
                        *(uint32_t*)(g_kh+base+r-64) = ph;
                        *(uint32_t*)(g_kl+base+r-64) = pl;
                    } else {
                        *(uint32_t*)(g_vh+base+r-128) = ph;
                        *(uint32_t*)(g_vl+base+r-128) = pl;
                    }
                } else {
                    float2 ov; ov.x = v0; ov.y = v1;
                    *(float2*)(Cout + (size_t)m*DD + n0) = ov;
                }
            }
        }
    }
}

// ---------------- flash attention on mma.sync (unchanged from R7) ----------------
#define ATILE 17408
#define QTILE 34816
#define ASMEM (QTILE + 4*ATILE)   // 104448

__global__ __launch_bounds__(256, 2)
void attn_mma(){
    extern __shared__ char smem[];
    const int bh = blockIdx.y;
    const int qt = (int)gridDim.x - 1 - (int)blockIdx.x;   // big tiles first
    const int qs = qt*128;
    const int tid = threadIdx.x, lane = tid&31, wid = tid>>5;
    uint32_t sb = smem_u32(smem);
    const uint32_t Qs = sb;
    const uint32_t Kb[2] = {sb + QTILE, sb + QTILE + ATILE};
    const uint32_t Vb[2] = {sb + QTILE + 2*ATILE, sb + QTILE + 3*ATILE};
    const size_t hb = (size_t)bh*SS*HDD;
    const bf16 *qh = g_qh+hb, *ql = g_ql+hb, *kh = g_kh+hb, *kl = g_kl+hb,
               *vh = g_vh+hb, *vl = g_vl+hb;

    #pragma unroll
    for (int i=0;i<8;i++){
        int id = i*256+tid, row = id>>4, seg = id&15;
        const bf16* src = (seg<8)? qh + (size_t)(qs+row)*HDD + seg*8
                                 : ql + (size_t)(qs+row)*HDD + (seg-8)*8;
        cp16(Qs + row*272 + seg*16, src);
    }
    cp_commit();

    auto load_kv = [&](int jt, int b){
        int ks = jt*64;
        #pragma unroll
        for (int i=0;i<4;i++){
            int id = i*256+tid, row = id>>4, seg = id&15;
            const bf16* src = (seg<8)? kh + (size_t)(ks+row)*HDD + seg*8
                                     : kl + (size_t)(ks+row)*HDD + (seg-8)*8;
            cp16(Kb[b] + row*272 + seg*16, src);
        }
        #pragma unroll
        for (int i=0;i<4;i++){
            int id = i*256+tid, row = id>>4, seg = id&15;
            const bf16* src = (seg<8)? vh + (size_t)(ks+row)*HDD + seg*8
                                     : vl + (size_t)(ks+row)*HDD + (seg-8)*8;
            cp16(Vb[b] + row*272 + seg*16, src);
        }
        cp_commit();
    };
    load_kv(0, 0);

    float o[8][4];
    #pragma unroll
    for (int a=0;a<8;a++)
        #pragma unroll
        for (int b=0;b<4;b++) o[a][b]=0.f;
    float m0 = -1e30f, m1 = -1e30f, l0 = 0.f, l1 = 0.f;
    const int rg0 = qs + wid*16 + (lane>>2);
    const int rg1 = rg0 + 8;
    const float SCL = 0.18033688f;   // 0.125 * log2(e)
    const int njt = 2*qt + 2;

    for (int jt=0; jt<njt; jt++){
        cp_wait<0>();
        __syncthreads();
        if (jt+1 < njt) load_kv(jt+1, (jt+1)&1);

        const int ks = jt*64;
        const uint32_t Kc = Kb[jt&1], Vc = Vb[jt&1];

        float s[8][4];
        #pragma unroll
        for (int a=0;a<8;a++)
            #pragma unroll
            for (int b=0;b<4;b++) s[a][b]=0.f;
        #pragma unroll
        for (int kc=0; kc<4; kc++){
            uint32_t qhf[4], qlf[4];
            uint32_t qa = Qs + (uint32_t)(wid*16 + (lane&15))*272
                        + kc*32 + ((lane>>4)<<4);
            ldsm4(qhf, qa); ldsm4(qlf, qa+128);
            uint32_t kt[4][4], ku[4][4];
            #pragma unroll
            for (int np=0; np<4; np++){
                uint32_t row = (uint32_t)(np*16 + ((lane>>4)<<3) + (lane&7));
                uint32_t ka = Kc + row*272 + kc*32 + (((lane>>3)&1)<<4);
                ldsm4(kt[np], ka); ldsm4(ku[np], ka+128);
            }
            #pragma unroll
            for (int np=0; np<4; np++){
                mma_bf(s[np*2],   qhf, kt[np][0], kt[np][1]);
                mma_bf(s[np*2+1], qhf, kt[np][2], kt[np][3]);
            }
            #pragma unroll
            for (int np=0; np<4; np++){
                mma_bf(s[np*2],   qhf, ku[np][0], ku[np][1]);
                mma_bf(s[np*2+1], qhf, ku[np][2], ku[np][3]);
            }
            #pragma unroll
            for (int np=0; np<4; np++){
                mma_bf(s[np*2],   qlf, kt[np][0], kt[np][1]);
                mma_bf(s[np*2+1], qlf, kt[np][2], kt[np][3]);
            }
        }
        const bool dia = (jt >= njt-2);
        #pragma unroll
        for (int nf=0; nf<8; nf++){
            int c = ks + nf*8 + ((lane&3)<<1);
            #pragma unroll
            for (int r=0;r<4;r++) s[nf][r] *= SCL;
            if (dia){
                if (c   > rg0) s[nf][0] = -1e30f;
                if (c+1 > rg0) s[nf][1] = -1e30f;
                if (c   > rg1) s[nf][2] = -1e30f;
                if (c+1 > rg1) s[nf][3] = -1e30f;
            }
        }
        float mx0 = -1e30f, mx1 = -1e30f;
        #pragma unroll
        for (int nf=0;nf<8;nf++){
            mx0 = fmaxf(mx0, fmaxf(s[nf][0], s[nf][1]));
            mx1 = fmaxf(mx1, fmaxf(s[nf][2], s[nf][3]));
        }
        mx0 = fmaxf(mx0, __shfl_xor_sync(0xffffffffu, mx0, 1));
        mx0 = fmaxf(mx0, __shfl_xor_sync(0xffffffffu, mx0, 2));
        mx1 = fmaxf(mx1, __shfl_xor_sync(0xffffffffu, mx1, 1));
        mx1 = fmaxf(mx1, __shfl_xor_sync(0xffffffffu, mx1, 2));
        float m0n = fmaxf(m0, mx0), m1n = fmaxf(m1, mx1);
        float a0 = ex2(m0 - m0n), a1 = ex2(m1 - m1n);
        m0 = m0n; m1 = m1n;

        float sum0 = 0.f, sum1 = 0.f;
        uint32_t ph[4][4], pl[4][4];
        #pragma unroll
        for (int kc=0; kc<4; kc++){
            #pragma unroll
            for (int half=0; half<2; half++){
                int nf = kc*2 + half;
                float p0 = ex2(s[nf][0]-m0n), p1 = ex2(s[nf][1]-m0n);
                float p2 = ex2(s[nf][2]-m1n), p3 = ex2(s[nf][3]-m1n);
                sum0 += p0+p1; sum1 += p2+p3;
                float h0=bfhi(p0), h1=bfhi(p1), h2=bfhi(p2), h3=bfhi(p3);
                ph[kc][half*2+0] = packbf(h0,h1);
                ph[kc][half*2+1] = packbf(h2,h3);
                pl[kc][half*2+0] = packbf(p0-h0, p1-h1);
                pl[kc][half*2+1] = packbf(p2-h2, p3-h3);
            }
        }
        sum0 += __shfl_xor_sync(0xffffffffu, sum0, 1);
        sum0 += __shfl_xor_sync(0xffffffffu, sum0, 2);
        sum1 += __shfl_xor_sync(0xffffffffu, sum1, 1);
        sum1 += __shfl_xor_sync(0xffffffffu, sum1, 2);
        l0 = l0*a0 + sum0; l1 = l1*a1 + sum1;
        #pragma unroll
        for (int nf=0;nf<8;nf++){
            o[nf][0]*=a0; o[nf][1]*=a0; o[nf][2]*=a1; o[nf][3]*=a1;
        }

        #pragma unroll
        for (int kc=0; kc<4; kc++){
            uint32_t vfh[4][4], vfl[4][4];
            #pragma unroll
            for (int g=0; g<4; g++){
                uint32_t va = Vc + (uint32_t)(kc*16 + (lane&15))*272
                            + ((uint32_t)(g*16 + ((lane>>4)<<3))<<1);
                ldsm4t(vfh[g], va);
                ldsm4t(vfl[g], va+128);
            }
            #pragma unroll
            for (int g=0; g<4; g++){
                mma_bf(o[g*2],   ph[kc], vfh[g][0], vfh[g][1]);
                mma_bf(o[g*2+1], ph[kc], vfh[g][2], vfh[g][3]);
            }
            #pragma unroll
            for (int g=0; g<4; g++){
                mma_bf(o[g*2],   ph[kc], vfl[g][0], vfl[g][1]);
                mma_bf(o[g*2+1], ph[kc], vfl[g][2], vfl[g][3]);
            }
            #pragma unroll
            for (int g=0; g<4; g++){
                mma_bf(o[g*2],   pl[kc], vfh[g][0], vfh[g][1]);
                mma_bf(o[g*2+1], pl[kc], vfh[g][2], vfh[g][3]);
            }
        }
    }

    // epilogue: o/l -> split bf16 -> g_aoh/g_aol[b*s][h*64+d]
    const int b = bh >> 4, h = bh & 15;
    float inv0 = 1.0f/l0, inv1 = 1.0f/l1;
    int r0 = qs + wid*16 + (lane>>2);
    #pragma unroll
    for (int nf=0; nf<8; nf++){
        int n0 = nf*8 + ((lane&3)<<1);
        float v0 = o[nf][0]*inv0, v1 = o[nf][1]*inv0;
        float h0 = bfhi(v0), h1 = bfhi(v1);
        size_t idx0 = ((size_t)(b*SS + r0))*DD + h*64 + n0;
        *(uint32_t*)(g_aoh + idx0) = packbf(h0,h1);
        *(uint32_t*)(g_aol + idx0) = packbf(v0-h0, v1-h1);
        float v2 = o[nf][2]*inv1, v3 = o[nf][3]*inv1;
        float h2 = bfhi(v2), h3 = bfhi(v3);
        size_t idx1 = ((size_t)(b*SS + r0 + 8))*DD + h*64 + n0;
        *(uint32_t*)(g_aoh + idx1) = packbf(h2,h3);
        *(uint32_t*)(g_aol + idx1) = packbf(v2-h2, v3-h3);
    }
}

// ---------------------------------------------------------------------------
extern "C" void kernel_launch(void* const* d_in, const int* in_sizes, int n_in,
                              void* d_out, int out_size) {
    (void)in_sizes; (void)n_in; (void)out_size;
    const float* x    = (const float*)d_in[0];
    const float* Wqkv = (const float*)d_in[1];
    const float* bqkv = (const float*)d_in[2];
    const float* Wout = (const float*)d_in[3];
    const float* bout = (const float*)d_in[4];
    float* out = (float*)d_out;

    cudaFuncSetAttribute(gemm_mma<0>, cudaFuncAttributeMaxDynamicSharedMemorySize, GSMEM);
    cudaFuncSetAttribute(gemm_mma<1>, cudaFuncAttributeMaxDynamicSharedMemorySize, GSMEM);
    cudaFuncSetAttribute(attn_mma,    cudaFuncAttributeMaxDynamicSharedMemorySize, ASMEM);

    // 0) split fp32 operands into (hi,lo) bf16
    split_k<0><<<(MTOT*DD/4 + 255)/256, 256>>>(x,    MTOT*DD/4);
    split_k<1><<<(DD*NQKV/4 + 255)/256, 256>>>(Wqkv, DD*NQKV/4);
    split_k<2><<<(DD*DD/4  + 255)/256, 256>>>(Wout,  DD*DD/4);

    // 1) QKV projection -> split q/k/v
    gemm_mma<0><<<dim3(NQKV/128, MTOT/128), 128, GSMEM>>>(bqkv, nullptr);

    // 2) causal attention -> g_aoh/g_aol
    attn_mma<<<dim3(SS/128, BHH), 256, ASMEM>>>();

    // 3) output projection -> out
    gemm_mma<1><<<dim3(DD/128, MTOT/128), 128, GSMEM>>>(bout, out);
}

// round 9
// speedup vs baseline: 1.5055x; 1.5055x over previous
#include <cuda_runtime.h>
#include <cuda_fp16.h>
#include <cstdint>

#define BB 2
#define SS 2048
#define DD 1024
#define HH 16
#define HDD 64
#define BHH 32
#define MTOT 4096
#define NQKV 3072

// operands (__device__ globals: allocation-free rule), 16B aligned
// A-side operands: single rounded fp16. B-side: hi+lo fp16.
__device__ __align__(16) __half g_xh[MTOT*DD];                     // x, single
__device__ __align__(16) __half g_wqh[DD*NQKV], g_wql[DD*NQKV];    // W_qkv [k][n] hi/lo
__device__ __align__(16) __half g_woh[DD*DD],   g_wol[DD*DD];      // W_out  [k][n] hi/lo
__device__ __align__(16) __half g_qh[BHH*SS*HDD];                  // q single [bh][s][hd]
__device__ __align__(16) __half g_kh[BHH*SS*HDD], g_kl[BHH*SS*HDD];
__device__ __align__(16) __half g_vh[BHH*SS*HDD], g_vl[BHH*SS*HDD];
__device__ __align__(16) __half g_ao[MTOT*DD];                     // attn out single [b*s][d]

// ---------------- helpers ----------------
__device__ __forceinline__ uint32_t smem_u32(const void* p){
    uint32_t a;
    asm("{ .reg .u64 t; cvta.to.shared.u64 t, %1; cvt.u32.u64 %0, t; }":"=r"(a):"l"(p));
    return a;
}
__device__ __forceinline__ void cp16(uint32_t d, const void* s){
    asm volatile("cp.async.cg.shared.global [%0], [%1], 16;"::"r"(d),"l"(s));
}
__device__ __forceinline__ void cp_commit(){ asm volatile("cp.async.commit_group;":::"memory"); }
template<int N> __device__ __forceinline__ void cp_wait(){
    asm volatile("cp.async.wait_group %0;"::"n"(N):"memory");
}
__device__ __forceinline__ void ldsm4(uint32_t* r, uint32_t a){
    asm volatile("ldmatrix.sync.aligned.m8n8.x4.shared.b16 {%0,%1,%2,%3}, [%4];"
        :"=r"(r[0]),"=r"(r[1]),"=r"(r[2]),"=r"(r[3]):"r"(a));
}
__device__ __forceinline__ void ldsm4t(uint32_t* r, uint32_t a){
    asm volatile("ldmatrix.sync.aligned.m8n8.x4.trans.shared.b16 {%0,%1,%2,%3}, [%4];"
        :"=r"(r[0]),"=r"(r[1]),"=r"(r[2]),"=r"(r[3]):"r"(a));
}
__device__ __forceinline__ void mma_h(float* c, const uint32_t* a, uint32_t b0, uint32_t b1){
    asm volatile("mma.sync.aligned.m16n8k16.row.col.f32.f16.f16.f32 "
        "{%0,%1,%2,%3}, {%4,%5,%6,%7}, {%8,%9}, {%0,%1,%2,%3};"
        :"+f"(c[0]),"+f"(c[1]),"+f"(c[2]),"+f"(c[3])
        :"r"(a[0]),"r"(a[1]),"r"(a[2]),"r"(a[3]),"r"(b0),"r"(b1));
}
__device__ __forceinline__ uint32_t packh(float x, float y){
    __half2 t = __floats2half2_rn(x, y);
    return *reinterpret_cast<uint32_t*>(&t);
}
__device__ __forceinline__ float hf(float v){
    return __half2float(__float2half_rn(v));
}
__device__ __forceinline__ float ex2(float x){
    float y; asm("ex2.approx.f32 %0, %1;":"=f"(y):"f"(x)); return y;
}

// ---------------- prep ----------------
// SEL 0: x -> single fp16.  SEL 1: W_qkv -> hi/lo.  SEL 2: W_out -> hi/lo.
template<int SEL>
__global__ __launch_bounds__(256)
void split_k(const float* __restrict__ src, int n4){
    int i = blockIdx.x*256 + threadIdx.x;
    if (i >= n4) return;
    float4 v = reinterpret_cast<const float4*>(src)[i];
    if (SEL == 0){
        reinterpret_cast<uint32_t*>(g_xh)[i*2+0] = packh(v.x, v.y);
        reinterpret_cast<uint32_t*>(g_xh)[i*2+1] = packh(v.z, v.w);
    } else {
        __half* hi = (SEL==1)? g_wqh : g_woh;
        __half* lo = (SEL==1)? g_wql : g_wol;
        float hx=hf(v.x), hy=hf(v.y), hz=hf(v.z), hw=hf(v.w);
        reinterpret_cast<uint32_t*>(hi)[i*2+0] = packh(hx,hy);
        reinterpret_cast<uint32_t*>(hi)[i*2+1] = packh(hz,hw);
        reinterpret_cast<uint32_t*>(lo)[i*2+0] = packh(v.x-hx, v.y-hy);
        reinterpret_cast<uint32_t*>(lo)[i*2+1] = packh(v.z-hz, v.w-hw);
    }
}

// ---------------- 2-term fp16 GEMM: 128x128 CTA tile, 8 warps of 64x32 ----------
// A tile: 128 rows x 32 fp16 (64B data, 80B stride)  -> 10240 B
// B tile:  32 k    x (128hi|128lo) fp16 (512B data, 528B stride) -> 16896 B
#define GSTAGE 27136
#define GSMEM  (3*GSTAGE)

template<int MODE>
__global__ __launch_bounds__(256, 2)
void gemm_mma(const float* __restrict__ bias, float* __restrict__ Cout){
    extern __shared__ char smem[];
    const __half* Ah  = (MODE==0)? g_xh  : g_ao;
    const __half* Bhi = (MODE==0)? g_wqh : g_woh;
    const __half* Blo = (MODE==0)? g_wql : g_wol;
    const int N = (MODE==0)? NQKV : DD;

    const int bm = blockIdx.y*128, bn = blockIdx.x*128;
    const int tid = threadIdx.x, lane = tid&31, wid = tid>>5;
    const int wm = wid>>2, wn = wid&3;   // warp tile 64(M) x 32(N)
    uint32_t sb = smem_u32(smem);

    float acc[4][4][4];
    #pragma unroll
    for (int a=0;a<4;a++)
        #pragma unroll
        for (int b=0;b<4;b++)
            #pragma unroll
            for (int c=0;c<4;c++) acc[a][b][c]=0.f;

    auto load_stage = [&](int t, int s){
        uint32_t as  = sb + s*GSTAGE;
        uint32_t bs2 = as + 10240;
        int k0 = t*32;
        // A: 512 x 16B
        #pragma unroll
        for (int i=0;i<2;i++){
            int id = i*256 + tid;
            int row = id>>2, seg = id&3;
            cp16(as + row*80 + seg*16, Ah + (size_t)(bm+row)*DD + k0 + seg*8);
        }
        // B: 1024 x 16B
        #pragma unroll
        for (int i=0;i<4;i++){
            int id = i*256 + tid;
            int row = id>>5, seg = id&31;
            const __half* src = (seg<16)? (Bhi + (size_t)(k0+row)*N + bn + seg*8)
                                        : (Blo + (size_t)(k0+row)*N + bn + (seg-16)*8);
            cp16(bs2 + row*528 + seg*16, src);
        }
        cp_commit();
    };

    load_stage(0,0);
    load_stage(1,1);
    int sl = 0, sl2 = 2;
    for (int t=0; t<32; t++){
        if (t<31) cp_wait<1>(); else cp_wait<0>();
        __syncthreads();
        if (t+2 < 32) load_stage(t+2, sl2);

        uint32_t as  = sb + sl*GSTAGE;
        uint32_t bs2 = as + 10240;
        #pragma unroll
        for (int k16=0;k16<2;k16++){
            uint32_t ah[4][4];
            #pragma unroll
            for (int mf=0;mf<4;mf++){
                uint32_t ad = as + (uint32_t)(wm*64+mf*16+(lane&15))*80
                            + k16*32 + ((lane>>4)<<4);
                ldsm4(ah[mf], ad);
            }
            uint32_t bhf[4][2], blf[4][2];
            #pragma unroll
            for (int np=0;np<2;np++){
                uint32_t kk = (uint32_t)(k16*16 + (lane&15));
                uint32_t bd = bs2 + kk*528
                            + ((uint32_t)(wn*32 + np*16 + ((lane>>4)<<3))<<1);
                uint32_t t4[4];
                ldsm4t(t4, bd);
                bhf[np*2][0]=t4[0]; bhf[np*2][1]=t4[1];
                bhf[np*2+1][0]=t4[2]; bhf[np*2+1][1]=t4[3];
                ldsm4t(t4, bd+256);
                blf[np*2][0]=t4[0]; blf[np*2][1]=t4[1];
                blf[np*2+1][0]=t4[2]; blf[np*2+1][1]=t4[3];
            }
            #pragma unroll
            for (int mf=0;mf<4;mf++)
                #pragma unroll
                for (int nf=0;nf<4;nf++)
                    mma_h(acc[mf][nf], ah[mf], bhf[nf][0], bhf[nf][1]);
            #pragma unroll
            for (int mf=0;mf<4;mf++)
                #pragma unroll
                for (int nf=0;nf<4;nf++)
                    mma_h(acc[mf][nf], ah[mf], blf[nf][0], blf[nf][1]);
        }
        sl  = (sl ==2)? 0 : sl+1;
        sl2 = (sl2==2)? 0 : sl2+1;
    }

    // epilogue
    #pragma unroll
    for (int mf=0;mf<4;mf++){
        #pragma unroll
        for (int nf=0;nf<4;nf++){
            int n0 = bn + wn*32 + nf*8 + ((lane&3)<<1);
            float b0v = bias[n0], b1v = bias[n0+1];
            #pragma unroll
            for (int hf2=0; hf2<2; hf2++){
                int m = bm + wm*64 + mf*16 + (lane>>2) + hf2*8;
                float v0 = acc[mf][nf][hf2*2+0] + b0v;
                float v1 = acc[mf][nf][hf2*2+1] + b1v;
                if (MODE==0){
                    int b = m>>11, s = m&(SS-1);
                    int h = n0/192, r = n0 - h*192;
                    size_t base = ((size_t)(b*HH+h)*SS + s)*HDD;
                    if (r < 64){
                        *(uint32_t*)(g_qh+base+r) = packh(v0,v1);   // q single
                    } else if (r < 128){
                        float h0 = hf(v0), h1 = hf(v1);
                        *(uint32_t*)(g_kh+base+r-64) = packh(h0,h1);
                        *(uint32_t*)(g_kl+base+r-64) = packh(v0-h0, v1-h1);
                    } else {
                        float h0 = hf(v0), h1 = hf(v1);
                        *(uint32_t*)(g_vh+base+r-128) = packh(h0,h1);
                        *(uint32_t*)(g_vl+base+r-128) = packh(v0-h0, v1-h1);
                    }
                } else {
                    float2 ov; ov.x = v0; ov.y = v1;
                    *(float2*)(Cout + (size_t)m*DD + n0) = ov;
                }
            }
        }
    }
}

// ---------------- flash attention, 2-term fp16 ----------------
// CTA: 128 q-rows, 8 warps (warp = 16 rows x 64 cols). k-tiles 64, K/V dbl-buffered.
// Q tile: 128 rows x 64 fp16 (128B data, 144B stride) -> 18432 B
// K/V tiles: 64 rows x (64hi|64lo) fp16 (256B data, 272B stride) -> 17408 B each
#define QTILE 18432
#define ATILE 17408
#define ASMEM (QTILE + 4*ATILE)   // 88064

__global__ __launch_bounds__(256, 2)
void attn_mma(){
    extern __shared__ char smem[];
    const int bh = blockIdx.y;
    const int qt = (int)gridDim.x - 1 - (int)blockIdx.x;   // big tiles first
    const int qs = qt*128;
    const int tid = threadIdx.x, lane = tid&31, wid = tid>>5;
    uint32_t sb = smem_u32(smem);
    const uint32_t Qs = sb;
    const uint32_t Kb[2] = {sb + QTILE, sb + QTILE + ATILE};
    const uint32_t Vb[2] = {sb + QTILE + 2*ATILE, sb + QTILE + 3*ATILE};
    const size_t hb = (size_t)bh*SS*HDD;
    const __half *qh = g_qh+hb, *kh = g_kh+hb, *kl = g_kl+hb,
                 *vh = g_vh+hb, *vl = g_vl+hb;

    // Q tile: 1024 x 16B
    #pragma unroll
    for (int i=0;i<4;i++){
        int id = i*256+tid, row = id>>3, seg = id&7;
        cp16(Qs + row*144 + seg*16, qh + (size_t)(qs+row)*HDD + seg*8);
    }
    cp_commit();

    auto load_kv = [&](int jt, int b){
        int ks = jt*64;
        #pragma unroll
        for (int i=0;i<4;i++){
            int id = i*256+tid, row = id>>4, seg = id&15;
            const __half* src = (seg<8)? kh + (size_t)(ks+row)*HDD + seg*8
                                       : kl + (size_t)(ks+row)*HDD + (seg-8)*8;
            cp16(Kb[b] + row*272 + seg*16, src);
        }
        #pragma unroll
        for (int i=0;i<4;i++){
            int id = i*256+tid, row = id>>4, seg = id&15;
            const __half* src = (seg<8)? vh + (size_t)(ks+row)*HDD + seg*8
                                       : vl + (size_t)(ks+row)*HDD + (seg-8)*8;
            cp16(Vb[b] + row*272 + seg*16, src);
        }
        cp_commit();
    };
    load_kv(0, 0);

    float o[8][4];
    #pragma unroll
    for (int a=0;a<8;a++)
        #pragma unroll
        for (int b=0;b<4;b++) o[a][b]=0.f;
    float m0 = -1e30f, m1 = -1e30f, l0 = 0.f, l1 = 0.f;
    const int rg0 = qs + wid*16 + (lane>>2);
    const int rg1 = rg0 + 8;
    const float SCL = 0.18033688f;   // 0.125 * log2(e)
    const int njt = 2*qt + 2;

    for (int jt=0; jt<njt; jt++){
        cp_wait<0>();
        __syncthreads();
        if (jt+1 < njt) load_kv(jt+1, (jt+1)&1);

        const int ks = jt*64;
        const uint32_t Kc = Kb[jt&1], Vc = Vb[jt&1];

        // S = Q K^T : q single fp16, K hi+lo (2 terms)
        float s[8][4];
        #pragma unroll
        for (int a=0;a<8;a++)
            #pragma unroll
            for (int b=0;b<4;b++) s[a][b]=0.f;
        #pragma unroll
        for (int kc=0; kc<4; kc++){
            uint32_t qf[4];
            uint32_t qa = Qs + (uint32_t)(wid*16 + (lane&15))*144
                        + kc*32 + ((lane>>4)<<4);
            ldsm4(qf, qa);
            uint32_t kt[4][4], ku[4][4];
            #pragma unroll
            for (int np=0; np<4; np++){
                uint32_t row = (uint32_t)(np*16 + ((lane>>4)<<3) + (lane&7));
                uint32_t ka = Kc + row*272 + kc*32 + (((lane>>3)&1)<<4);
                ldsm4(kt[np], ka); ldsm4(ku[np], ka+128);
            }
            #pragma unroll
            for (int np=0; np<4; np++){
                mma_h(s[np*2],   qf, kt[np][0], kt[np][1]);
                mma_h(s[np*2+1], qf, kt[np][2], kt[np][3]);
            }
            #pragma unroll
            for (int np=0; np<4; np++){
                mma_h(s[np*2],   qf, ku[np][0], ku[np][1]);
                mma_h(s[np*2+1], qf, ku[np][2], ku[np][3]);
            }
        }
        // scale (log2 domain) + causal mask on the two diagonal tiles
        const bool dia = (jt >= njt-2);
        #pragma unroll
        for (int nf=0; nf<8; nf++){
            int c = ks + nf*8 + ((lane&3)<<1);
            #pragma unroll
            for (int r=0;r<4;r++) s[nf][r] *= SCL;
            if (dia){
                if (c   > rg0) s[nf][0] = -1e30f;
                if (c+1 > rg0) s[nf][1] = -1e30f;
                if (c   > rg1) s[nf][2] = -1e30f;
                if (c+1 > rg1) s[nf][3] = -1e30f;
            }
        }
        // row maxima
        float mx0 = -1e30f, mx1 = -1e30f;
        #pragma unroll
        for (int nf=0;nf<8;nf++){
            mx0 = fmaxf(mx0, fmaxf(s[nf][0], s[nf][1]));
            mx1 = fmaxf(mx1, fmaxf(s[nf][2], s[nf][3]));
        }
        mx0 = fmaxf(mx0, __shfl_xor_sync(0xffffffffu, mx0, 1));
        mx0 = fmaxf(mx0, __shfl_xor_sync(0xffffffffu, mx0, 2));
        mx1 = fmaxf(mx1, __shfl_xor_sync(0xffffffffu, mx1, 1));
        mx1 = fmaxf(mx1, __shfl_xor_sync(0xffffffffu, mx1, 2));
        float m0n = fmaxf(m0, mx0), m1n = fmaxf(m1, mx1);
        float a0 = ex2(m0 - m0n), a1 = ex2(m1 - m1n);
        m0 = m0n; m1 = m1n;

        // P = 2^(S - m): single fp16 (row sums in fp32 stay exact)
        float sum0 = 0.f, sum1 = 0.f;
        uint32_t ph[4][4];
        #pragma unroll
        for (int kc=0; kc<4; kc++){
            #pragma unroll
            for (int half=0; half<2; half++){
                int nf = kc*2 + half;
                float p0 = ex2(s[nf][0]-m0n), p1 = ex2(s[nf][1]-m0n);
                float p2 = ex2(s[nf][2]-m1n), p3 = ex2(s[nf][3]-m1n);
                sum0 += p0+p1; sum1 += p2+p3;
                ph[kc][half*2+0] = packh(p0,p1);
                ph[kc][half*2+1] = packh(p2,p3);
            }
        }
        sum0 += __shfl_xor_sync(0xffffffffu, sum0, 1);
        sum0 += __shfl_xor_sync(0xffffffffu, sum0, 2);
        sum1 += __shfl_xor_sync(0xffffffffu, sum1, 1);
        sum1 += __shfl_xor_sync(0xffffffffu, sum1, 2);
        l0 = l0*a0 + sum0; l1 = l1*a1 + sum1;
        #pragma unroll
        for (int nf=0;nf<8;nf++){
            o[nf][0]*=a0; o[nf][1]*=a0; o[nf][2]*=a1; o[nf][3]*=a1;
        }

        // O += P @ (Vh + Vl) : 2 terms
        #pragma unroll
        for (int kc=0; kc<4; kc++){
            uint32_t vfh[4][4], vfl[4][4];
            #pragma unroll
            for (int g=0; g<4; g++){
                uint32_t va = Vc + (uint32_t)(kc*16 + (lane&15))*272
                            + ((uint32_t)(g*16 + ((lane>>4)<<3))<<1);
                ldsm4t(vfh[g], va);
                ldsm4t(vfl[g], va+128);
            }
            #pragma unroll
            for (int g=0; g<4; g++){
                mma_h(o[g*2],   ph[kc], vfh[g][0], vfh[g][1]);
                mma_h(o[g*2+1], ph[kc], vfh[g][2], vfh[g][3]);
            }
            #pragma unroll
            for (int g=0; g<4; g++){
                mma_h(o[g*2],   ph[kc], vfl[g][0], vfl[g][1]);
                mma_h(o[g*2+1], ph[kc], vfl[g][2], vfl[g][3]);
            }
        }
    }

    // epilogue: o/l -> single fp16 -> g_ao[b*s][h*64+d]
    const int b = bh >> 4, h = bh & 15;
    float inv0 = 1.0f/l0, inv1 = 1.0f/l1;
    int r0 = qs + wid*16 + (lane>>2);
    #pragma unroll
    for (int nf=0; nf<8; nf++){
        int n0 = nf*8 + ((lane&3)<<1);
        size_t idx0 = ((size_t)(b*SS + r0))*DD + h*64 + n0;
        *(uint32_t*)(g_ao + idx0) = packh(o[nf][0]*inv0, o[nf][1]*inv0);
        size_t idx1 = ((size_t)(b*SS + r0 + 8))*DD + h*64 + n0;
        *(uint32_t*)(g_ao + idx1) = packh(o[nf][2]*inv1, o[nf][3]*inv1);
    }
}

// ---------------------------------------------------------------------------
extern "C" void kernel_launch(void* const* d_in, const int* in_sizes, int n_in,
                              void* d_out, int out_size) {
    (void)in_sizes; (void)n_in; (void)out_size;
    const float* x    = (const float*)d_in[0];
    const float* Wqkv = (const float*)d_in[1];
    const float* bqkv = (const float*)d_in[2];
    const float* Wout = (const float*)d_in[3];
    const float* bout = (const float*)d_in[4];
    float* out = (float*)d_out;

    cudaFuncSetAttribute(gemm_mma<0>, cudaFuncAttributeMaxDynamicSharedMemorySize, GSMEM);
    cudaFuncSetAttribute(gemm_mma<1>, cudaFuncAttributeMaxDynamicSharedMemorySize, GSMEM);
    cudaFuncSetAttribute(attn_mma,    cudaFuncAttributeMaxDynamicSharedMemorySize, ASMEM);

    // 0) convert/split operands
    split_k<0><<<(MTOT*DD/4 + 255)/256, 256>>>(x,    MTOT*DD/4);
    split_k<1><<<(DD*NQKV/4 + 255)/256, 256>>>(Wqkv, DD*NQKV/4);
    split_k<2><<<(DD*DD/4  + 255)/256, 256>>>(Wout,  DD*DD/4);

    // 1) QKV projection -> q (single), k/v (hi+lo)
    gemm_mma<0><<<dim3(NQKV/128, MTOT/128), 256, GSMEM>>>(bqkv, nullptr);

    // 2) causal attention -> g_ao (single fp16)
    attn_mma<<<dim3(SS/128, BHH), 256, ASMEM>>>();

    // 3) output projection -> out
    gemm_mma<1><<<dim3(DD/128, MTOT/128), 256, GSMEM>>>(bout, out);
}

// round 10
// speedup vs baseline: 1.8031x; 1.1977x over previous
#include <cuda_runtime.h>
#include <cuda_fp16.h>
#include <cstdint>

#define BB 2
#define SS 2048
#define DD 1024
#define HH 16
#define HDD 64
#define BHH 32
#define MTOT 4096
#define NQKV 3072

// operands (__device__ globals: allocation-free rule), 16B aligned
// GEMM A-side + all attention operands: single rounded fp16. GEMM B-side: hi+lo.
__device__ __align__(16) __half g_xh[MTOT*DD];                     // x, single
__device__ __align__(16) __half g_wqh[DD*NQKV], g_wql[DD*NQKV];    // W_qkv [k][n] hi/lo
__device__ __align__(16) __half g_woh[DD*DD],   g_wol[DD*DD];      // W_out  [k][n] hi/lo
__device__ __align__(16) __half g_qh[BHH*SS*HDD];                  // q single [bh][s][hd]
__device__ __align__(16) __half g_kh[BHH*SS*HDD];                  // k single
__device__ __align__(16) __half g_vh[BHH*SS*HDD];                  // v single
__device__ __align__(16) __half g_ao[MTOT*DD];                     // attn out single [b*s][d]

// ---------------- helpers ----------------
__device__ __forceinline__ uint32_t smem_u32(const void* p){
    uint32_t a;
    asm("{ .reg .u64 t; cvta.to.shared.u64 t, %1; cvt.u32.u64 %0, t; }":"=r"(a):"l"(p));
    return a;
}
__device__ __forceinline__ void cp16(uint32_t d, const void* s){
    asm volatile("cp.async.cg.shared.global [%0], [%1], 16;"::"r"(d),"l"(s));
}
__device__ __forceinline__ void cp_commit(){ asm volatile("cp.async.commit_group;":::"memory"); }
template<int N> __device__ __forceinline__ void cp_wait(){
    asm volatile("cp.async.wait_group %0;"::"n"(N):"memory");
}
__device__ __forceinline__ void ldsm4(uint32_t* r, uint32_t a){
    asm volatile("ldmatrix.sync.aligned.m8n8.x4.shared.b16 {%0,%1,%2,%3}, [%4];"
        :"=r"(r[0]),"=r"(r[1]),"=r"(r[2]),"=r"(r[3]):"r"(a));
}
__device__ __forceinline__ void ldsm4t(uint32_t* r, uint32_t a){
    asm volatile("ldmatrix.sync.aligned.m8n8.x4.trans.shared.b16 {%0,%1,%2,%3}, [%4];"
        :"=r"(r[0]),"=r"(r[1]),"=r"(r[2]),"=r"(r[3]):"r"(a));
}
__device__ __forceinline__ void mma_h(float* c, const uint32_t* a, uint32_t b0, uint32_t b1){
    asm volatile("mma.sync.aligned.m16n8k16.row.col.f32.f16.f16.f32 "
        "{%0,%1,%2,%3}, {%4,%5,%6,%7}, {%8,%9}, {%0,%1,%2,%3};"
        :"+f"(c[0]),"+f"(c[1]),"+f"(c[2]),"+f"(c[3])
        :"r"(a[0]),"r"(a[1]),"r"(a[2]),"r"(a[3]),"r"(b0),"r"(b1));
}
__device__ __forceinline__ uint32_t packh(float x, float y){
    __half2 t = __floats2half2_rn(x, y);
    return *reinterpret_cast<uint32_t*>(&t);
}
__device__ __forceinline__ float hf(float v){
    return __half2float(__float2half_rn(v));
}
__device__ __forceinline__ float ex2(float x){
    float y; asm("ex2.approx.f32 %0, %1;":"=f"(y):"f"(x)); return y;
}

// ---------------- prep ----------------
// SEL 0: x -> single fp16.  SEL 1: W_qkv -> hi/lo.  SEL 2: W_out -> hi/lo.
template<int SEL>
__global__ __launch_bounds__(256)
void split_k(const float* __restrict__ src, int n4){
    int i = blockIdx.x*256 + threadIdx.x;
    if (i >= n4) return;
    float4 v = reinterpret_cast<const float4*>(src)[i];
    if (SEL == 0){
        reinterpret_cast<uint32_t*>(g_xh)[i*2+0] = packh(v.x, v.y);
        reinterpret_cast<uint32_t*>(g_xh)[i*2+1] = packh(v.z, v.w);
    } else {
        __half* hi = (SEL==1)? g_wqh : g_woh;
        __half* lo = (SEL==1)? g_wql : g_wol;
        float hx=hf(v.x), hy=hf(v.y), hz=hf(v.z), hw=hf(v.w);
        reinterpret_cast<uint32_t*>(hi)[i*2+0] = packh(hx,hy);
        reinterpret_cast<uint32_t*>(hi)[i*2+1] = packh(hz,hw);
        reinterpret_cast<uint32_t*>(lo)[i*2+0] = packh(v.x-hx, v.y-hy);
        reinterpret_cast<uint32_t*>(lo)[i*2+1] = packh(v.z-hz, v.w-hw);
    }
}

// ---------------- 2-term fp16 GEMM: 128x128 CTA tile, 8 warps of 64x32 ----------
// A tile: 128 rows x 32 fp16 (64B data, 80B stride)  -> 10240 B
// B tile:  32 k    x (128hi|128lo) fp16 (512B data, 528B stride) -> 16896 B
#define GSTAGE 27136
#define GSMEM  (3*GSTAGE)

template<int MODE>
__global__ __launch_bounds__(256, 2)
void gemm_mma(const float* __restrict__ bias, float* __restrict__ Cout){
    extern __shared__ char smem[];
    const __half* Ah  = (MODE==0)? g_xh  : g_ao;
    const __half* Bhi = (MODE==0)? g_wqh : g_woh;
    const __half* Blo = (MODE==0)? g_wql : g_wol;
    const int N = (MODE==0)? NQKV : DD;

    const int bm = blockIdx.y*128, bn = blockIdx.x*128;
    const int tid = threadIdx.x, lane = tid&31, wid = tid>>5;
    const int wm = wid>>2, wn = wid&3;   // warp tile 64(M) x 32(N)
    uint32_t sb = smem_u32(smem);

    float acc[4][4][4];
    #pragma unroll
    for (int a=0;a<4;a++)
        #pragma unroll
        for (int b=0;b<4;b++)
            #pragma unroll
            for (int c=0;c<4;c++) acc[a][b][c]=0.f;

    auto load_stage = [&](int t, int s){
        uint32_t as  = sb + s*GSTAGE;
        uint32_t bs2 = as + 10240;
        int k0 = t*32;
        #pragma unroll
        for (int i=0;i<2;i++){
            int id = i*256 + tid;
            int row = id>>2, seg = id&3;
            cp16(as + row*80 + seg*16, Ah + (size_t)(bm+row)*DD + k0 + seg*8);
        }
        #pragma unroll
        for (int i=0;i<4;i++){
            int id = i*256 + tid;
            int row = id>>5, seg = id&31;
            const __half* src = (seg<16)? (Bhi + (size_t)(k0+row)*N + bn + seg*8)
                                        : (Blo + (size_t)(k0+row)*N + bn + (seg-16)*8);
            cp16(bs2 + row*528 + seg*16, src);
        }
        cp_commit();
    };

    load_stage(0,0);
    load_stage(1,1);
    int sl = 0, sl2 = 2;
    for (int t=0; t<32; t++){
        if (t<31) cp_wait<1>(); else cp_wait<0>();
        __syncthreads();
        if (t+2 < 32) load_stage(t+2, sl2);

        uint32_t as  = sb + sl*GSTAGE;
        uint32_t bs2 = as + 10240;
        #pragma unroll
        for (int k16=0;k16<2;k16++){
            uint32_t ah[4][4];
            #pragma unroll
            for (int mf=0;mf<4;mf++){
                uint32_t ad = as + (uint32_t)(wm*64+mf*16+(lane&15))*80
                            + k16*32 + ((lane>>4)<<4);
                ldsm4(ah[mf], ad);
            }
            uint32_t bhf[4][2], blf[4][2];
            #pragma unroll
            for (int np=0;np<2;np++){
                uint32_t kk = (uint32_t)(k16*16 + (lane&15));
                uint32_t bd = bs2 + kk*528
                            + ((uint32_t)(wn*32 + np*16 + ((lane>>4)<<3))<<1);
                uint32_t t4[4];
                ldsm4t(t4, bd);
                bhf[np*2][0]=t4[0]; bhf[np*2][1]=t4[1];
                bhf[np*2+1][0]=t4[2]; bhf[np*2+1][1]=t4[3];
                ldsm4t(t4, bd+256);
                blf[np*2][0]=t4[0]; blf[np*2][1]=t4[1];
                blf[np*2+1][0]=t4[2]; blf[np*2+1][1]=t4[3];
            }
            #pragma unroll
            for (int mf=0;mf<4;mf++)
                #pragma unroll
                for (int nf=0;nf<4;nf++)
                    mma_h(acc[mf][nf], ah[mf], bhf[nf][0], bhf[nf][1]);
            #pragma unroll
            for (int mf=0;mf<4;mf++)
                #pragma unroll
                for (int nf=0;nf<4;nf++)
                    mma_h(acc[mf][nf], ah[mf], blf[nf][0], blf[nf][1]);
        }
        sl  = (sl ==2)? 0 : sl+1;
        sl2 = (sl2==2)? 0 : sl2+1;
    }

    // epilogue
    #pragma unroll
    for (int mf=0;mf<4;mf++){
        #pragma unroll
        for (int nf=0;nf<4;nf++){
            int n0 = bn + wn*32 + nf*8 + ((lane&3)<<1);
            float b0v = bias[n0], b1v = bias[n0+1];
            #pragma unroll
            for (int hf2=0; hf2<2; hf2++){
                int m = bm + wm*64 + mf*16 + (lane>>2) + hf2*8;
                float v0 = acc[mf][nf][hf2*2+0] + b0v;
                float v1 = acc[mf][nf][hf2*2+1] + b1v;
                if (MODE==0){
                    int b = m>>11, s = m&(SS-1);
                    int h = n0/192, r = n0 - h*192;
                    size_t base = ((size_t)(b*HH+h)*SS + s)*HDD;
                    if (r < 64)       *(uint32_t*)(g_qh+base+r)     = packh(v0,v1);
                    else if (r < 128) *(uint32_t*)(g_kh+base+r-64)  = packh(v0,v1);
                    else              *(uint32_t*)(g_vh+base+r-128) = packh(v0,v1);
                } else {
                    float2 ov; ov.x = v0; ov.y = v1;
                    *(float2*)(Cout + (size_t)m*DD + n0) = ov;
                }
            }
        }
    }
}

// ---------------- flash attention, single fp16 operands ----------------
// CTA: 128 q-rows, 8 warps (warp = 16 rows x 64 cols). k-tiles 64, K/V dbl-buffered.
// Q tile: 128 rows x 64 fp16 (128B data, 144B stride) -> 18432 B
// K/V tiles: 64 rows x 64 fp16 (128B data, 144B stride) -> 9216 B each
#define QTILE 18432
#define KTILE 9216
#define ASMEM (QTILE + 4*KTILE)   // 55296

__global__ __launch_bounds__(256, 2)
void attn_mma(){
    extern __shared__ char smem[];
    const int bh = blockIdx.y;
    const int qt = (int)gridDim.x - 1 - (int)blockIdx.x;   // big tiles first
    const int qs = qt*128;
    const int tid = threadIdx.x, lane = tid&31, wid = tid>>5;
    uint32_t sb = smem_u32(smem);
    const uint32_t Qs = sb;
    const uint32_t Kb[2] = {sb + QTILE, sb + QTILE + KTILE};
    const uint32_t Vb[2] = {sb + QTILE + 2*KTILE, sb + QTILE + 3*KTILE};
    const size_t hb = (size_t)bh*SS*HDD;
    const __half *qh = g_qh+hb, *kh = g_kh+hb, *vh = g_vh+hb;

    // Q tile: 1024 x 16B
    #pragma unroll
    for (int i=0;i<4;i++){
        int id = i*256+tid, row = id>>3, seg = id&7;
        cp16(Qs + row*144 + seg*16, qh + (size_t)(qs+row)*HDD + seg*8);
    }
    cp_commit();

    auto load_kv = [&](int jt, int b){
        int ks = jt*64;
        #pragma unroll
        for (int i=0;i<2;i++){
            int id = i*256+tid, row = id>>3, seg = id&7;
            cp16(Kb[b] + row*144 + seg*16, kh + (size_t)(ks+row)*HDD + seg*8);
        }
        #pragma unroll
        for (int i=0;i<2;i++){
            int id = i*256+tid, row = id>>3, seg = id&7;
            cp16(Vb[b] + row*144 + seg*16, vh + (size_t)(ks+row)*HDD + seg*8);
        }
        cp_commit();
    };
    load_kv(0, 0);

    float o[8][4];
    #pragma unroll
    for (int a=0;a<8;a++)
        #pragma unroll
        for (int b=0;b<4;b++) o[a][b]=0.f;
    float m0 = -1e30f, m1 = -1e30f, l0 = 0.f, l1 = 0.f;
    const int rg0 = qs + wid*16 + (lane>>2);
    const int rg1 = rg0 + 8;
    const float SCL = 0.18033688f;   // 0.125 * log2(e)
    const int njt = 2*qt + 2;

    for (int jt=0; jt<njt; jt++){
        cp_wait<0>();
        __syncthreads();
        if (jt+1 < njt) load_kv(jt+1, (jt+1)&1);

        const int ks = jt*64;
        const uint32_t Kc = Kb[jt&1], Vc = Vb[jt&1];

        // S = Q K^T, single term
        float s[8][4];
        #pragma unroll
        for (int a=0;a<8;a++)
            #pragma unroll
            for (int b=0;b<4;b++) s[a][b]=0.f;
        #pragma unroll
        for (int kc=0; kc<4; kc++){
            uint32_t qf[4];
            uint32_t qa = Qs + (uint32_t)(wid*16 + (lane&15))*144
                        + kc*32 + ((lane>>4)<<4);
            ldsm4(qf, qa);
            uint32_t kt[4][4];
            #pragma unroll
            for (int np=0; np<4; np++){
                uint32_t row = (uint32_t)(np*16 + ((lane>>4)<<3) + (lane&7));
                uint32_t ka = Kc + row*144 + kc*32 + (((lane>>3)&1)<<4);
                ldsm4(kt[np], ka);
            }
            #pragma unroll
            for (int np=0; np<4; np++){
                mma_h(s[np*2],   qf, kt[np][0], kt[np][1]);
                mma_h(s[np*2+1], qf, kt[np][2], kt[np][3]);
            }
        }
        // scale (log2 domain) + causal mask on the two diagonal tiles
        const bool dia = (jt >= njt-2);
        #pragma unroll
        for (int nf=0; nf<8; nf++){
            int c = ks + nf*8 + ((lane&3)<<1);
            #pragma unroll
            for (int r=0;r<4;r++) s[nf][r] *= SCL;
            if (dia){
                if (c   > rg0) s[nf][0] = -1e30f;
                if (c+1 > rg0) s[nf][1] = -1e30f;
                if (c   > rg1) s[nf][2] = -1e30f;
                if (c+1 > rg1) s[nf][3] = -1e30f;
            }
        }
        // row maxima
        float mx0 = -1e30f, mx1 = -1e30f;
        #pragma unroll
        for (int nf=0;nf<8;nf++){
            mx0 = fmaxf(mx0, fmaxf(s[nf][0], s[nf][1]));
            mx1 = fmaxf(mx1, fmaxf(s[nf][2], s[nf][3]));
        }
        mx0 = fmaxf(mx0, __shfl_xor_sync(0xffffffffu, mx0, 1));
        mx0 = fmaxf(mx0, __shfl_xor_sync(0xffffffffu, mx0, 2));
        mx1 = fmaxf(mx1, __shfl_xor_sync(0xffffffffu, mx1, 1));
        mx1 = fmaxf(mx1, __shfl_xor_sync(0xffffffffu, mx1, 2));
        float m0n = fmaxf(m0, mx0), m1n = fmaxf(m1, mx1);
        float a0 = ex2(m0 - m0n), a1 = ex2(m1 - m1n);
        m0 = m0n; m1 = m1n;

        // P = 2^(S - m): single fp16 (row sums in fp32 stay exact)
        float sum0 = 0.f, sum1 = 0.f;
        uint32_t ph[4][4];
        #pragma unroll
        for (int kc=0; kc<4; kc++){
            #pragma unroll
            for (int half=0; half<2; half++){
                int nf = kc*2 + half;
                float p0 = ex2(s[nf][0]-m0n), p1 = ex2(s[nf][1]-m0n);
                float p2 = ex2(s[nf][2]-m1n), p3 = ex2(s[nf][3]-m1n);
                sum0 += p0+p1; sum1 += p2+p3;
                ph[kc][half*2+0] = packh(p0,p1);
                ph[kc][half*2+1] = packh(p2,p3);
            }
        }
        sum0 += __shfl_xor_sync(0xffffffffu, sum0, 1);
        sum0 += __shfl_xor_sync(0xffffffffu, sum0, 2);
        sum1 += __shfl_xor_sync(0xffffffffu, sum1, 1);
        sum1 += __shfl_xor_sync(0xffffffffu, sum1, 2);
        l0 = l0*a0 + sum0; l1 = l1*a1 + sum1;
        #pragma unroll
        for (int nf=0;nf<8;nf++){
            o[nf][0]*=a0; o[nf][1]*=a0; o[nf][2]*=a1; o[nf][3]*=a1;
        }

        // O += P @ V, single term
        #pragma unroll
        for (int kc=0; kc<4; kc++){
            uint32_t vf[4][4];
            #pragma unroll
            for (int g=0; g<4; g++){
                uint32_t va = Vc + (uint32_t)(kc*16 + (lane&15))*144
                            + ((uint32_t)(g*16 + ((lane>>4)<<3))<<1);
                ldsm4t(vf[g], va);
            }
            #pragma unroll
            for (int g=0; g<4; g++){
                mma_h(o[g*2],   ph[kc], vf[g][0], vf[g][1]);
                mma_h(o[g*2+1], ph[kc], vf[g][2], vf[g][3]);
            }
        }
    }

    // epilogue: o/l -> single fp16 -> g_ao[b*s][h*64+d]
    const int b = bh >> 4, h = bh & 15;
    float inv0 = 1.0f/l0, inv1 = 1.0f/l1;
    int r0 = qs + wid*16 + (lane>>2);
    #pragma unroll
    for (int nf=0; nf<8; nf++){
        int n0 = nf*8 + ((lane&3)<<1);
        size_t idx0 = ((size_t)(b*SS + r0))*DD + h*64 + n0;
        *(uint32_t*)(g_ao + idx0) = packh(o[nf][0]*inv0, o[nf][1]*inv0);
        size_t idx1 = ((size_t)(b*SS + r0 + 8))*DD + h*64 + n0;
        *(uint32_t*)(g_ao + idx1) = packh(o[nf][2]*inv1, o[nf][3]*inv1);
    }
}

// ---------------------------------------------------------------------------
extern "C" void kernel_launch(void* const* d_in, const int* in_sizes, int n_in,
                              void* d_out, int out_size) {
    (void)in_sizes; (void)n_in; (void)out_size;
    const float* x    = (const float*)d_in[0];
    const float* Wqkv = (const float*)d_in[1];
    const float* bqkv = (const float*)d_in[2];
    const float* Wout = (const float*)d_in[3];
    const float* bout = (const float*)d_in[4];
    float* out = (float*)d_out;

    cudaFuncSetAttribute(gemm_mma<0>, cudaFuncAttributeMaxDynamicSharedMemorySize, GSMEM);
    cudaFuncSetAttribute(gemm_mma<1>, cudaFuncAttributeMaxDynamicSharedMemorySize, GSMEM);
    cudaFuncSetAttribute(attn_mma,    cudaFuncAttributeMaxDynamicSharedMemorySize, ASMEM);

    // 0) convert/split operands
    split_k<0><<<(MTOT*DD/4 + 255)/256, 256>>>(x,    MTOT*DD/4);
    split_k<1><<<(DD*NQKV/4 + 255)/256, 256>>>(Wqkv, DD*NQKV/4);
    split_k<2><<<(DD*DD/4  + 255)/256, 256>>>(Wout,  DD*DD/4);

    // 1) QKV projection -> q/k/v single fp16
    gemm_mma<0><<<dim3(NQKV/128, MTOT/128), 256, GSMEM>>>(bqkv, nullptr);

    // 2) causal attention -> g_ao (single fp16)
    attn_mma<<<dim3(SS/128, BHH), 256, ASMEM>>>();

    // 3) output projection -> out
    gemm_mma<1><<<dim3(DD/128, MTOT/128), 256, GSMEM>>>(bout, out);
}

// round 11
// speedup vs baseline: 2.3369x; 1.2960x over previous
#include <cuda_runtime.h>
#include <cuda_fp16.h>
#include <cstdint>

#define BB 2
#define SS 2048
#define DD 1024
#define HH 16
#define HDD 64
#define BHH 32
#define MTOT 4096
#define NQKV 3072

// operands (__device__ globals: allocation-free rule), 16B aligned
// All MMA operands single rounded fp16; fp32 accumulate everywhere.
__device__ __align__(16) __half g_xh[MTOT*DD];                     // x [m][k]
__device__ __align__(16) __half g_wqh[DD*NQKV];                    // W_qkv [k][n]
__device__ __align__(16) __half g_woh[DD*DD];                      // W_out  [k][n]
__device__ __align__(16) __half g_qh[BHH*SS*HDD];                  // q [bh][s][hd]
__device__ __align__(16) __half g_kh[BHH*SS*HDD];                  // k
__device__ __align__(16) __half g_vh[BHH*SS*HDD];                  // v
__device__ __align__(16) __half g_ao[MTOT*DD];                     // attn out [b*s][d]

// ---------------- helpers ----------------
__device__ __forceinline__ uint32_t smem_u32(const void* p){
    uint32_t a;
    asm("{ .reg .u64 t; cvta.to.shared.u64 t, %1; cvt.u32.u64 %0, t; }":"=r"(a):"l"(p));
    return a;
}
__device__ __forceinline__ void cp16(uint32_t d, const void* s){
    asm volatile("cp.async.cg.shared.global [%0], [%1], 16;"::"r"(d),"l"(s));
}
__device__ __forceinline__ void cp_commit(){ asm volatile("cp.async.commit_group;":::"memory"); }
template<int N> __device__ __forceinline__ void cp_wait(){
    asm volatile("cp.async.wait_group %0;"::"n"(N):"memory");
}
__device__ __forceinline__ void ldsm4(uint32_t* r, uint32_t a){
    asm volatile("ldmatrix.sync.aligned.m8n8.x4.shared.b16 {%0,%1,%2,%3}, [%4];"
        :"=r"(r[0]),"=r"(r[1]),"=r"(r[2]),"=r"(r[3]):"r"(a));
}
__device__ __forceinline__ void ldsm4t(uint32_t* r, uint32_t a){
    asm volatile("ldmatrix.sync.aligned.m8n8.x4.trans.shared.b16 {%0,%1,%2,%3}, [%4];"
        :"=r"(r[0]),"=r"(r[1]),"=r"(r[2]),"=r"(r[3]):"r"(a));
}
__device__ __forceinline__ void mma_h(float* c, const uint32_t* a, uint32_t b0, uint32_t b1){
    asm volatile("mma.sync.aligned.m16n8k16.row.col.f32.f16.f16.f32 "
        "{%0,%1,%2,%3}, {%4,%5,%6,%7}, {%8,%9}, {%0,%1,%2,%3};"
        :"+f"(c[0]),"+f"(c[1]),"+f"(c[2]),"+f"(c[3])
        :"r"(a[0]),"r"(a[1]),"r"(a[2]),"r"(a[3]),"r"(b0),"r"(b1));
}
__device__ __forceinline__ uint32_t packh(float x, float y){
    __half2 t = __floats2half2_rn(x, y);
    return *reinterpret_cast<uint32_t*>(&t);
}
__device__ __forceinline__ float ex2(float x){
    float y; asm("ex2.approx.f32 %0, %1;":"=f"(y):"f"(x)); return y;
}

// ---------------- prep: fp32 -> fp16 ----------------
// SEL 0: x.  SEL 1: W_qkv.  SEL 2: W_out.
template<int SEL>
__global__ __launch_bounds__(256)
void conv_h(const float* __restrict__ src, int n4){
    __half* dst = (SEL==0)? g_xh : (SEL==1)? g_wqh : g_woh;
    int i = blockIdx.x*256 + threadIdx.x;
    if (i >= n4) return;
    float4 v = reinterpret_cast<const float4*>(src)[i];
    reinterpret_cast<uint32_t*>(dst)[i*2+0] = packh(v.x, v.y);
    reinterpret_cast<uint32_t*>(dst)[i*2+1] = packh(v.z, v.w);
}

// ---------------- fp16 GEMM: 128x128 CTA tile, 8 warps of 64x32 ----------
// A tile: 128 rows x 32 fp16 (64B data, 80B stride)   -> 10240 B
// B tile:  32 k    x 128 fp16 (256B data, 272B stride) -> 8704 B
#define GSTAGE 18944
#define GSMEM  (3*GSTAGE)

template<int MODE>
__global__ __launch_bounds__(256, 2)
void gemm_mma(const float* __restrict__ bias, float* __restrict__ Cout){
    extern __shared__ char smem[];
    const __half* Ah = (MODE==0)? g_xh  : g_ao;
    const __half* Bh = (MODE==0)? g_wqh : g_woh;
    const int N = (MODE==0)? NQKV : DD;

    const int bm = blockIdx.y*128, bn = blockIdx.x*128;
    const int tid = threadIdx.x, lane = tid&31, wid = tid>>5;
    const int wm = wid>>2, wn = wid&3;   // warp tile 64(M) x 32(N)
    uint32_t sb = smem_u32(smem);

    float acc[4][4][4];
    #pragma unroll
    for (int a=0;a<4;a++)
        #pragma unroll
        for (int b=0;b<4;b++)
            #pragma unroll
            for (int c=0;c<4;c++) acc[a][b][c]=0.f;

    auto load_stage = [&](int t, int s){
        uint32_t as  = sb + s*GSTAGE;
        uint32_t bs2 = as + 10240;
        int k0 = t*32;
        // A: 512 x 16B
        #pragma unroll
        for (int i=0;i<2;i++){
            int id = i*256 + tid;
            int row = id>>2, seg = id&3;
            cp16(as + row*80 + seg*16, Ah + (size_t)(bm+row)*DD + k0 + seg*8);
        }
        // B: 512 x 16B
        #pragma unroll
        for (int i=0;i<2;i++){
            int id = i*256 + tid;
            int row = id>>4, seg = id&15;
            cp16(bs2 + row*272 + seg*16, Bh + (size_t)(k0+row)*N + bn + seg*8);
        }
        cp_commit();
    };

    load_stage(0,0);
    load_stage(1,1);
    int sl = 0, sl2 = 2;
    for (int t=0; t<32; t++){
        if (t<31) cp_wait<1>(); else cp_wait<0>();
        __syncthreads();
        if (t+2 < 32) load_stage(t+2, sl2);

        uint32_t as  = sb + sl*GSTAGE;
        uint32_t bs2 = as + 10240;
        #pragma unroll
        for (int k16=0;k16<2;k16++){
            uint32_t ah[4][4];
            #pragma unroll
            for (int mf=0;mf<4;mf++){
                uint32_t ad = as + (uint32_t)(wm*64+mf*16+(lane&15))*80
                            + k16*32 + ((lane>>4)<<4);
                ldsm4(ah[mf], ad);
            }
            uint32_t bhf[4][2];
            #pragma unroll
            for (int np=0;np<2;np++){
                uint32_t kk = (uint32_t)(k16*16 + (lane&15));
                uint32_t bd = bs2 + kk*272
                            + ((uint32_t)(wn*32 + np*16 + ((lane>>4)<<3))<<1);
                uint32_t t4[4];
                ldsm4t(t4, bd);
                bhf[np*2][0]=t4[0]; bhf[np*2][1]=t4[1];
                bhf[np*2+1][0]=t4[2]; bhf[np*2+1][1]=t4[3];
            }
            #pragma unroll
            for (int mf=0;mf<4;mf++)
                #pragma unroll
                for (int nf=0;nf<4;nf++)
                    mma_h(acc[mf][nf], ah[mf], bhf[nf][0], bhf[nf][1]);
        }
        sl  = (sl ==2)? 0 : sl+1;
        sl2 = (sl2==2)? 0 : sl2+1;
    }

    // epilogue
    #pragma unroll
    for (int mf=0;mf<4;mf++){
        #pragma unroll
        for (int nf=0;nf<4;nf++){
            int n0 = bn + wn*32 + nf*8 + ((lane&3)<<1);
            float b0v = bias[n0], b1v = bias[n0+1];
            #pragma unroll
            for (int hf2=0; hf2<2; hf2++){
                int m = bm + wm*64 + mf*16 + (lane>>2) + hf2*8;
                float v0 = acc[mf][nf][hf2*2+0] + b0v;
                float v1 = acc[mf][nf][hf2*2+1] + b1v;
                if (MODE==0){
                    int b = m>>11, s = m&(SS-1);
                    int h = n0/192, r = n0 - h*192;
                    size_t base = ((size_t)(b*HH+h)*SS + s)*HDD;
                    if (r < 64)       *(uint32_t*)(g_qh+base+r)     = packh(v0,v1);
                    else if (r < 128) *(uint32_t*)(g_kh+base+r-64)  = packh(v0,v1);
                    else              *(uint32_t*)(g_vh+base+r-128) = packh(v0,v1);
                } else {
                    float2 ov; ov.x = v0; ov.y = v1;
                    *(float2*)(Cout + (size_t)m*DD + n0) = ov;
                }
            }
        }
    }
}

// ---------------- flash attention, single fp16 operands ----------------
// CTA: 128 q-rows, 8 warps (warp = 16 rows x 64 cols). k-tiles 64, K/V dbl-buffered.
// Q tile: 128 rows x 64 fp16 (128B data, 144B stride) -> 18432 B
// K/V tiles: 64 rows x 64 fp16 (128B data, 144B stride) -> 9216 B each
#define QTILE 18432
#define KTILE 9216
#define ASMEM (QTILE + 4*KTILE)   // 55296

__global__ __launch_bounds__(256, 2)
void attn_mma(){
    extern __shared__ char smem[];
    const int bh = blockIdx.y;
    const int qt = (int)gridDim.x - 1 - (int)blockIdx.x;   // big tiles first
    const int qs = qt*128;
    const int tid = threadIdx.x, lane = tid&31, wid = tid>>5;
    uint32_t sb = smem_u32(smem);
    const uint32_t Qs = sb;
    const uint32_t Kb[2] = {sb + QTILE, sb + QTILE + KTILE};
    const uint32_t Vb[2] = {sb + QTILE + 2*KTILE, sb + QTILE + 3*KTILE};
    const size_t hb = (size_t)bh*SS*HDD;
    const __half *qh = g_qh+hb, *kh = g_kh+hb, *vh = g_vh+hb;

    // Q tile: 1024 x 16B
    #pragma unroll
    for (int i=0;i<4;i++){
        int id = i*256+tid, row = id>>3, seg = id&7;
        cp16(Qs + row*144 + seg*16, qh + (size_t)(qs+row)*HDD + seg*8);
    }
    cp_commit();

    auto load_kv = [&](int jt, int b){
        int ks = jt*64;
        #pragma unroll
        for (int i=0;i<2;i++){
            int id = i*256+tid, row = id>>3, seg = id&7;
            cp16(Kb[b] + row*144 + seg*16, kh + (size_t)(ks+row)*HDD + seg*8);
        }
        #pragma unroll
        for (int i=0;i<2;i++){
            int id = i*256+tid, row = id>>3, seg = id&7;
            cp16(Vb[b] + row*144 + seg*16, vh + (size_t)(ks+row)*HDD + seg*8);
        }
        cp_commit();
    };
    load_kv(0, 0);

    float o[8][4];
    #pragma unroll
    for (int a=0;a<8;a++)
        #pragma unroll
        for (int b=0;b<4;b++) o[a][b]=0.f;
    float m0 = -1e30f, m1 = -1e30f, l0 = 0.f, l1 = 0.f;
    const int rg0 = qs + wid*16 + (lane>>2);
    const int rg1 = rg0 + 8;
    const float SCL = 0.18033688f;   // 0.125 * log2(e)
    const int njt = 2*qt + 2;

    for (int jt=0; jt<njt; jt++){
        cp_wait<0>();
        __syncthreads();
        if (jt+1 < njt) load_kv(jt+1, (jt+1)&1);

        const int ks = jt*64;
        const uint32_t Kc = Kb[jt&1], Vc = Vb[jt&1];

        // S = Q K^T, single term
        float s[8][4];
        #pragma unroll
        for (int a=0;a<8;a++)
            #pragma unroll
            for (int b=0;b<4;b++) s[a][b]=0.f;
        #pragma unroll
        for (int kc=0; kc<4; kc++){
            uint32_t qf[4];
            uint32_t qa = Qs + (uint32_t)(wid*16 + (lane&15))*144
                        + kc*32 + ((lane>>4)<<4);
            ldsm4(qf, qa);
            uint32_t kt[4][4];
            #pragma unroll
            for (int np=0; np<4; np++){
                uint32_t row = (uint32_t)(np*16 + ((lane>>4)<<3) + (lane&7));
                uint32_t ka = Kc + row*144 + kc*32 + (((lane>>3)&1)<<4);
                ldsm4(kt[np], ka);
            }
            #pragma unroll
            for (int np=0; np<4; np++){
                mma_h(s[np*2],   qf, kt[np][0], kt[np][1]);
                mma_h(s[np*2+1], qf, kt[np][2], kt[np][3]);
            }
        }
        // scale (log2 domain) + causal mask on the two diagonal tiles
        const bool dia = (jt >= njt-2);
        #pragma unroll
        for (int nf=0; nf<8; nf++){
            int c = ks + nf*8 + ((lane&3)<<1);
            #pragma unroll
            for (int r=0;r<4;r++) s[nf][r] *= SCL;
            if (dia){
                if (c   > rg0) s[nf][0] = -1e30f;
                if (c+1 > rg0) s[nf][1] = -1e30f;
                if (c   > rg1) s[nf][2] = -1e30f;
                if (c+1 > rg1) s[nf][3] = -1e30f;
            }
        }
        // row maxima
        float mx0 = -1e30f, mx1 = -1e30f;
        #pragma unroll
        for (int nf=0;nf<8;nf++){
            mx0 = fmaxf(mx0, fmaxf(s[nf][0], s[nf][1]));
            mx1 = fmaxf(mx1, fmaxf(s[nf][2], s[nf][3]));
        }
        mx0 = fmaxf(mx0, __shfl_xor_sync(0xffffffffu, mx0, 1));
        mx0 = fmaxf(mx0, __shfl_xor_sync(0xffffffffu, mx0, 2));
        mx1 = fmaxf(mx1, __shfl_xor_sync(0xffffffffu, mx1, 1));
        mx1 = fmaxf(mx1, __shfl_xor_sync(0xffffffffu, mx1, 2));
        float m0n = fmaxf(m0, mx0), m1n = fmaxf(m1, mx1);
        float a0 = ex2(m0 - m0n), a1 = ex2(m1 - m1n);
        m0 = m0n; m1 = m1n;

        // P = 2^(S - m): single fp16 (row sums in fp32 stay exact)
        float sum0 = 0.f, sum1 = 0.f;
        uint32_t ph[4][4];
        #pragma unroll
        for (int kc=0; kc<4; kc++){
            #pragma unroll
            for (int half=0; half<2; half++){
                int nf = kc*2 + half;
                float p0 = ex2(s[nf][0]-m0n), p1 = ex2(s[nf][1]-m0n);
                float p2 = ex2(s[nf][2]-m1n), p3 = ex2(s[nf][3]-m1n);
                sum0 += p0+p1; sum1 += p2+p3;
                ph[kc][half*2+0] = packh(p0,p1);
                ph[kc][half*2+1] = packh(p2,p3);
            }
        }
        sum0 += __shfl_xor_sync(0xffffffffu, sum0, 1);
        sum0 += __shfl_xor_sync(0xffffffffu, sum0, 2);
        sum1 += __shfl_xor_sync(0xffffffffu, sum1, 1);
        sum1 += __shfl_xor_sync(0xffffffffu, sum1, 2);
        l0 = l0*a0 + sum0; l1 = l1*a1 + sum1;
        #pragma unroll
        for (int nf=0;nf<8;nf++){
            o[nf][0]*=a0; o[nf][1]*=a0; o[nf][2]*=a1; o[nf][3]*=a1;
        }

        // O += P @ V, single term
        #pragma unroll
        for (int kc=0; kc<4; kc++){
            uint32_t vf[4][4];
            #pragma unroll
            for (int g=0; g<4; g++){
                uint32_t va = Vc + (uint32_t)(kc*16 + (lane&15))*144
                            + ((uint32_t)(g*16 + ((lane>>4)<<3))<<1);
                ldsm4t(vf[g], va);
            }
            #pragma unroll
            for (int g=0; g<4; g++){
                mma_h(o[g*2],   ph[kc], vf[g][0], vf[g][1]);
                mma_h(o[g*2+1], ph[kc], vf[g][2], vf[g][3]);
            }
        }
    }

    // epilogue: o/l -> fp16 -> g_ao[b*s][h*64+d]
    const int b = bh >> 4, h = bh & 15;
    float inv0 = 1.0f/l0, inv1 = 1.0f/l1;
    int r0 = qs + wid*16 + (lane>>2);
    #pragma unroll
    for (int nf=0; nf<8; nf++){
        int n0 = nf*8 + ((lane&3)<<1);
        size_t idx0 = ((size_t)(b*SS + r0))*DD + h*64 + n0;
        *(uint32_t*)(g_ao + idx0) = packh(o[nf][0]*inv0, o[nf][1]*inv0);
        size_t idx1 = ((size_t)(b*SS + r0 + 8))*DD + h*64 + n0;
        *(uint32_t*)(g_ao + idx1) = packh(o[nf][2]*inv1, o[nf][3]*inv1);
    }
}

// ---------------------------------------------------------------------------
extern "C" void kernel_launch(void* const* d_in, const int* in_sizes, int n_in,
                              void* d_out, int out_size) {
    (void)in_sizes; (void)n_in; (void)out_size;
    const float* x    = (const float*)d_in[0];
    const float* Wqkv = (const float*)d_in[1];
    const float* bqkv = (const float*)d_in[2];
    const float* Wout = (const float*)d_in[3];
    const float* bout = (const float*)d_in[4];
    float* out = (float*)d_out;

    cudaFuncSetAttribute(gemm_mma<0>, cudaFuncAttributeMaxDynamicSharedMemorySize, GSMEM);
    cudaFuncSetAttribute(gemm_mma<1>, cudaFuncAttributeMaxDynamicSharedMemorySize, GSMEM);
    cudaFuncSetAttribute(attn_mma,    cudaFuncAttributeMaxDynamicSharedMemorySize, ASMEM);

    // 0) convert operands to fp16
    conv_h<0><<<(MTOT*DD/4 + 255)/256, 256>>>(x,    MTOT*DD/4);
    conv_h<1><<<(DD*NQKV/4 + 255)/256, 256>>>(Wqkv, DD*NQKV/4);
    conv_h<2><<<(DD*DD/4  + 255)/256, 256>>>(Wout,  DD*DD/4);

    // 1) QKV projection -> q/k/v fp16
    gemm_mma<0><<<dim3(NQKV/128, MTOT/128), 256, GSMEM>>>(bqkv, nullptr);

    // 2) causal attention -> g_ao (fp16)
    attn_mma<<<dim3(SS/128, BHH), 256, ASMEM>>>();

    // 3) output projection -> out
    gemm_mma<1><<<dim3(DD/128, MTOT/128), 256, GSMEM>>>(bout, out);
}

// round 12
// speedup vs baseline: 2.4963x; 1.0682x over previous
#include <cuda_runtime.h>
#include <cuda_fp16.h>
#include <cstdint>

#define BB 2
#define SS 2048
#define DD 1024
#define HH 16
#define HDD 64
#define BHH 32
#define MTOT 4096
#define NQKV 3072

// operands (__device__ globals: allocation-free rule), 16B aligned
// All MMA operands single rounded fp16; fp32 accumulate everywhere.
__device__ __align__(16) __half g_xh[MTOT*DD];                     // x [m][k]
__device__ __align__(16) __half g_wqh[DD*NQKV];                    // W_qkv [k][n]
__device__ __align__(16) __half g_woh[DD*DD];                      // W_out  [k][n]
__device__ __align__(16) __half g_qh[BHH*SS*HDD];                  // q [bh][s][hd]
__device__ __align__(16) __half g_kh[BHH*SS*HDD];                  // k
__device__ __align__(16) __half g_vh[BHH*SS*HDD];                  // v
__device__ __align__(16) __half g_ao[MTOT*DD];                     // attn out [b*s][d]

// ---------------- helpers ----------------
__device__ __forceinline__ uint32_t smem_u32(const void* p){
    uint32_t a;
    asm("{ .reg .u64 t; cvta.to.shared.u64 t, %1; cvt.u32.u64 %0, t; }":"=r"(a):"l"(p));
    return a;
}
__device__ __forceinline__ void cp16(uint32_t d, const void* s){
    asm volatile("cp.async.cg.shared.global [%0], [%1], 16;"::"r"(d),"l"(s));
}
__device__ __forceinline__ void cp_commit(){ asm volatile("cp.async.commit_group;":::"memory"); }
template<int N> __device__ __forceinline__ void cp_wait(){
    asm volatile("cp.async.wait_group %0;"::"n"(N):"memory");
}
__device__ __forceinline__ void ldsm4(uint32_t* r, uint32_t a){
    asm volatile("ldmatrix.sync.aligned.m8n8.x4.shared.b16 {%0,%1,%2,%3}, [%4];"
        :"=r"(r[0]),"=r"(r[1]),"=r"(r[2]),"=r"(r[3]):"r"(a));
}
__device__ __forceinline__ void ldsm4t(uint32_t* r, uint32_t a){
    asm volatile("ldmatrix.sync.aligned.m8n8.x4.trans.shared.b16 {%0,%1,%2,%3}, [%4];"
        :"=r"(r[0]),"=r"(r[1]),"=r"(r[2]),"=r"(r[3]):"r"(a));
}
__device__ __forceinline__ void mma_h(float* c, const uint32_t* a, uint32_t b0, uint32_t b1){
    asm volatile("mma.sync.aligned.m16n8k16.row.col.f32.f16.f16.f32 "
        "{%0,%1,%2,%3}, {%4,%5,%6,%7}, {%8,%9}, {%0,%1,%2,%3};"
        :"+f"(c[0]),"+f"(c[1]),"+f"(c[2]),"+f"(c[3])
        :"r"(a[0]),"r"(a[1]),"r"(a[2]),"r"(a[3]),"r"(b0),"r"(b1));
}
__device__ __forceinline__ uint32_t packh(float x, float y){
    __half2 t = __floats2half2_rn(x, y);
    return *reinterpret_cast<uint32_t*>(&t);
}
__device__ __forceinline__ float ex2(float x){
    float y; asm("ex2.approx.f32 %0, %1;":"=f"(y):"f"(x)); return y;
}

// ---------------- prep: fp32 -> fp16 ----------------
template<int SEL>
__global__ __launch_bounds__(256)
void conv_h(const float* __restrict__ src, int n4){
    __half* dst = (SEL==0)? g_xh : (SEL==1)? g_wqh : g_woh;
    int i = blockIdx.x*256 + threadIdx.x;
    if (i >= n4) return;
    float4 v = reinterpret_cast<const float4*>(src)[i];
    reinterpret_cast<uint32_t*>(dst)[i*2+0] = packh(v.x, v.y);
    reinterpret_cast<uint32_t*>(dst)[i*2+1] = packh(v.z, v.w);
}

// ---------------- fp16 GEMM: 128x128 CTA tile, 4 warps of 64x64 ----------
// A tile: 128 rows x 32 fp16 (64B data, 80B stride)   -> 10240 B
// B tile:  32 k    x 128 fp16 (256B data, 272B stride) -> 8704 B
#define GSTAGE 18944
#define GSMEM  (3*GSTAGE)

template<int MODE>
__global__ __launch_bounds__(128, 2)
void gemm_mma(const float* __restrict__ bias, float* __restrict__ Cout){
    extern __shared__ char smem[];
    const __half* Ah = (MODE==0)? g_xh  : g_ao;
    const __half* Bh = (MODE==0)? g_wqh : g_woh;
    const int N = (MODE==0)? NQKV : DD;

    const int bm = blockIdx.y*128, bn = blockIdx.x*128;
    const int tid = threadIdx.x, lane = tid&31, wid = tid>>5;
    const int wm = wid>>1, wn = wid&1;   // warp tile 64(M) x 64(N)
    uint32_t sb = smem_u32(smem);

    float acc[4][8][4];
    #pragma unroll
    for (int a=0;a<4;a++)
        #pragma unroll
        for (int b=0;b<8;b++)
            #pragma unroll
            for (int c=0;c<4;c++) acc[a][b][c]=0.f;

    auto load_stage = [&](int t, int s){
        uint32_t as  = sb + s*GSTAGE;
        uint32_t bs2 = as + 10240;
        int k0 = t*32;
        // A: 512 x 16B
        #pragma unroll
        for (int i=0;i<4;i++){
            int id = i*128 + tid;
            int row = id>>2, seg = id&3;
            cp16(as + row*80 + seg*16, Ah + (size_t)(bm+row)*DD + k0 + seg*8);
        }
        // B: 512 x 16B
        #pragma unroll
        for (int i=0;i<4;i++){
            int id = i*128 + tid;
            int row = id>>4, seg = id&15;
            cp16(bs2 + row*272 + seg*16, Bh + (size_t)(k0+row)*N + bn + seg*8);
        }
        cp_commit();
    };

    load_stage(0,0);
    load_stage(1,1);
    int sl = 0, sl2 = 2;
    for (int t=0; t<32; t++){
        if (t<31) cp_wait<1>(); else cp_wait<0>();
        __syncthreads();
        if (t+2 < 32) load_stage(t+2, sl2);

        uint32_t as  = sb + sl*GSTAGE;
        uint32_t bs2 = as + 10240;
        #pragma unroll
        for (int k16=0;k16<2;k16++){
            uint32_t ah[4][4];
            #pragma unroll
            for (int mf=0;mf<4;mf++){
                uint32_t ad = as + (uint32_t)(wm*64+mf*16+(lane&15))*80
                            + k16*32 + ((lane>>4)<<4);
                ldsm4(ah[mf], ad);
            }
            uint32_t bhf[8][2];
            #pragma unroll
            for (int g=0;g<4;g++){
                uint32_t kk = (uint32_t)(k16*16 + (lane&15));
                uint32_t bd = bs2 + kk*272
                            + ((uint32_t)(wn*64 + g*16 + ((lane>>4)<<3))<<1);
                uint32_t t4[4];
                ldsm4t(t4, bd);
                bhf[g*2][0]=t4[0]; bhf[g*2][1]=t4[1];
                bhf[g*2+1][0]=t4[2]; bhf[g*2+1][1]=t4[3];
            }
            #pragma unroll
            for (int mf=0;mf<4;mf++)
                #pragma unroll
                for (int nf=0;nf<8;nf++)
                    mma_h(acc[mf][nf], ah[mf], bhf[nf][0], bhf[nf][1]);
        }
        sl  = (sl ==2)? 0 : sl+1;
        sl2 = (sl2==2)? 0 : sl2+1;
    }

    // epilogue
    #pragma unroll
    for (int mf=0;mf<4;mf++){
        #pragma unroll
        for (int nf=0;nf<8;nf++){
            int n0 = bn + wn*64 + nf*8 + ((lane&3)<<1);
            float b0v = bias[n0], b1v = bias[n0+1];
            #pragma unroll
            for (int hf2=0; hf2<2; hf2++){
                int m = bm + wm*64 + mf*16 + (lane>>2) + hf2*8;
                float v0 = acc[mf][nf][hf2*2+0] + b0v;
                float v1 = acc[mf][nf][hf2*2+1] + b1v;
                if (MODE==0){
                    int b = m>>11, s = m&(SS-1);
                    int h = n0/192, r = n0 - h*192;
                    size_t base = ((size_t)(b*HH+h)*SS + s)*HDD;
                    if (r < 64)       *(uint32_t*)(g_qh+base+r)     = packh(v0,v1);
                    else if (r < 128) *(uint32_t*)(g_kh+base+r-64)  = packh(v0,v1);
                    else              *(uint32_t*)(g_vh+base+r-128) = packh(v0,v1);
                } else {
                    float2 ov; ov.x = v0; ov.y = v1;
                    *(float2*)(Cout + (size_t)m*DD + n0) = ov;
                }
            }
        }
    }
}

// ---------------- flash attention, single fp16 operands (unchanged) ----------------
// CTA: 128 q-rows, 8 warps (warp = 16 rows x 64 cols). k-tiles 64, K/V dbl-buffered.
#define QTILE 18432
#define KTILE 9216
#define ASMEM (QTILE + 4*KTILE)   // 55296

__global__ __launch_bounds__(256, 2)
void attn_mma(){
    extern __shared__ char smem[];
    const int bh = blockIdx.y;
    const int qt = (int)gridDim.x - 1 - (int)blockIdx.x;   // big tiles first
    const int qs = qt*128;
    const int tid = threadIdx.x, lane = tid&31, wid = tid>>5;
    uint32_t sb = smem_u32(smem);
    const uint32_t Qs = sb;
    const uint32_t Kb[2] = {sb + QTILE, sb + QTILE + KTILE};
    const uint32_t Vb[2] = {sb + QTILE + 2*KTILE, sb + QTILE + 3*KTILE};
    const size_t hb = (size_t)bh*SS*HDD;
    const __half *qh = g_qh+hb, *kh = g_kh+hb, *vh = g_vh+hb;

    // Q tile: 1024 x 16B
    #pragma unroll
    for (int i=0;i<4;i++){
        int id = i*256+tid, row = id>>3, seg = id&7;
        cp16(Qs + row*144 + seg*16, qh + (size_t)(qs+row)*HDD + seg*8);
    }
    cp_commit();

    auto load_kv = [&](int jt, int b){
        int ks = jt*64;
        #pragma unroll
        for (int i=0;i<2;i++){
            int id = i*256+tid, row = id>>3, seg = id&7;
            cp16(Kb[b] + row*144 + seg*16, kh + (size_t)(ks+row)*HDD + seg*8);
        }
        #pragma unroll
        for (int i=0;i<2;i++){
            int id = i*256+tid, row = id>>3, seg = id&7;
            cp16(Vb[b] + row*144 + seg*16, vh + (size_t)(ks+row)*HDD + seg*8);
        }
        cp_commit();
    };
    load_kv(0, 0);

    float o[8][4];
    #pragma unroll
    for (int a=0;a<8;a++)
        #pragma unroll
        for (int b=0;b<4;b++) o[a][b]=0.f;
    float m0 = -1e30f, m1 = -1e30f, l0 = 0.f, l1 = 0.f;
    const int rg0 = qs + wid*16 + (lane>>2);
    const int rg1 = rg0 + 8;
    const float SCL = 0.18033688f;   // 0.125 * log2(e)
    const int njt = 2*qt + 2;

    for (int jt=0; jt<njt; jt++){
        cp_wait<0>();
        __syncthreads();
        if (jt+1 < njt) load_kv(jt+1, (jt+1)&1);

        const int ks = jt*64;
        const uint32_t Kc = Kb[jt&1], Vc = Vb[jt&1];

        // S = Q K^T, single term
        float s[8][4];
        #pragma unroll
        for (int a=0;a<8;a++)
            #pragma unroll
            for (int b=0;b<4;b++) s[a][b]=0.f;
        #pragma unroll
        for (int kc=0; kc<4; kc++){
            uint32_t qf[4];
            uint32_t qa = Qs + (uint32_t)(wid*16 + (lane&15))*144
                        + kc*32 + ((lane>>4)<<4);
            ldsm4(qf, qa);
            uint32_t kt[4][4];
            #pragma unroll
            for (int np=0; np<4; np++){
                uint32_t row = (uint32_t)(np*16 + ((lane>>4)<<3) + (lane&7));
                uint32_t ka = Kc + row*144 + kc*32 + (((lane>>3)&1)<<4);
                ldsm4(kt[np], ka);
            }
            #pragma unroll
            for (int np=0; np<4; np++){
                mma_h(s[np*2],   qf, kt[np][0], kt[np][1]);
                mma_h(s[np*2+1], qf, kt[np][2], kt[np][3]);
            }
        }
        // scale (log2 domain) + causal mask on the two diagonal tiles
        const bool dia = (jt >= njt-2);
        #pragma unroll
        for (int nf=0; nf<8; nf++){
            int c = ks + nf*8 + ((lane&3)<<1);
            #pragma unroll
            for (int r=0;r<4;r++) s[nf][r] *= SCL;
            if (dia){
                if (c   > rg0) s[nf][0] = -1e30f;
                if (c+1 > rg0) s[nf][1] = -1e30f;
                if (c   > rg1) s[nf][2] = -1e30f;
                if (c+1 > rg1) s[nf][3] = -1e30f;
            }
        }
        // row maxima
        float mx0 = -1e30f, mx1 = -1e30f;
        #pragma unroll
        for (int nf=0;nf<8;nf++){
            mx0 = fmaxf(mx0, fmaxf(s[nf][0], s[nf][1]));
            mx1 = fmaxf(mx1, fmaxf(s[nf][2], s[nf][3]));
        }
        mx0 = fmaxf(mx0, __shfl_xor_sync(0xffffffffu, mx0, 1));
        mx0 = fmaxf(mx0, __shfl_xor_sync(0xffffffffu, mx0, 2));
        mx1 = fmaxf(mx1, __shfl_xor_sync(0xffffffffu, mx1, 1));
        mx1 = fmaxf(mx1, __shfl_xor_sync(0xffffffffu, mx1, 2));
        float m0n = fmaxf(m0, mx0), m1n = fmaxf(m1, mx1);
        float a0 = ex2(m0 - m0n), a1 = ex2(m1 - m1n);
        m0 = m0n; m1 = m1n;

        // P = 2^(S - m): single fp16 (row sums in fp32 stay exact)
        float sum0 = 0.f, sum1 = 0.f;
        uint32_t ph[4][4];
        #pragma unroll
        for (int kc=0; kc<4; kc++){
            #pragma unroll
            for (int half=0; half<2; half++){
                int nf = kc*2 + half;
                float p0 = ex2(s[nf][0]-m0n), p1 = ex2(s[nf][1]-m0n);
                float p2 = ex2(s[nf][2]-m1n), p3 = ex2(s[nf][3]-m1n);
                sum0 += p0+p1; sum1 += p2+p3;
                ph[kc][half*2+0] = packh(p0,p1);
                ph[kc][half*2+1] = packh(p2,p3);
            }
        }
        sum0 += __shfl_xor_sync(0xffffffffu, sum0, 1);
        sum0 += __shfl_xor_sync(0xffffffffu, sum0, 2);
        sum1 += __shfl_xor_sync(0xffffffffu, sum1, 1);
        sum1 += __shfl_xor_sync(0xffffffffu, sum1, 2);
        l0 = l0*a0 + sum0; l1 = l1*a1 + sum1;
        #pragma unroll
        for (int nf=0;nf<8;nf++){
            o[nf][0]*=a0; o[nf][1]*=a0; o[nf][2]*=a1; o[nf][3]*=a1;
        }

        // O += P @ V, single term
        #pragma unroll
        for (int kc=0; kc<4; kc++){
            uint32_t vf[4][4];
            #pragma unroll
            for (int g=0; g<4; g++){
                uint32_t va = Vc + (uint32_t)(kc*16 + (lane&15))*144
                            + ((uint32_t)(g*16 + ((lane>>4)<<3))<<1);
                ldsm4t(vf[g], va);
            }
            #pragma unroll
            for (int g=0; g<4; g++){
                mma_h(o[g*2],   ph[kc], vf[g][0], vf[g][1]);
                mma_h(o[g*2+1], ph[kc], vf[g][2], vf[g][3]);
            }
        }
    }

    // epilogue: o/l -> fp16 -> g_ao[b*s][h*64+d]
    const int b = bh >> 4, h = bh & 15;
    float inv0 = 1.0f/l0, inv1 = 1.0f/l1;
    int r0 = qs + wid*16 + (lane>>2);
    #pragma unroll
    for (int nf=0; nf<8; nf++){
        int n0 = nf*8 + ((lane&3)<<1);
        size_t idx0 = ((size_t)(b*SS + r0))*DD + h*64 + n0;
        *(uint32_t*)(g_ao + idx0) = packh(o[nf][0]*inv0, o[nf][1]*inv0);
        size_t idx1 = ((size_t)(b*SS + r0 + 8))*DD + h*64 + n0;
        *(uint32_t*)(g_ao + idx1) = packh(o[nf][2]*inv1, o[nf][3]*inv1);
    }
}

// ---------------------------------------------------------------------------
extern "C" void kernel_launch(void* const* d_in, const int* in_sizes, int n_in,
                              void* d_out, int out_size) {
    (void)in_sizes; (void)n_in; (void)out_size;
    const float* x    = (const float*)d_in[0];
    const float* Wqkv = (const float*)d_in[1];
    const float* bqkv = (const float*)d_in[2];
    const float* Wout = (const float*)d_in[3];
    const float* bout = (const float*)d_in[4];
    float* out = (float*)d_out;

    cudaFuncSetAttribute(gemm_mma<0>, cudaFuncAttributeMaxDynamicSharedMemorySize, GSMEM);
    cudaFuncSetAttribute(gemm_mma<1>, cudaFuncAttributeMaxDynamicSharedMemorySize, GSMEM);
    cudaFuncSetAttribute(attn_mma,    cudaFuncAttributeMaxDynamicSharedMemorySize, ASMEM);

    // 0) convert operands to fp16
    conv_h<0><<<(MTOT*DD/4 + 255)/256, 256>>>(x,    MTOT*DD/4);
    conv_h<1><<<(DD*NQKV/4 + 255)/256, 256>>>(Wqkv, DD*NQKV/4);
    conv_h<2><<<(DD*DD/4  + 255)/256, 256>>>(Wout,  DD*DD/4);

    // 1) QKV projection -> q/k/v fp16
    gemm_mma<0><<<dim3(NQKV/128, MTOT/128), 128, GSMEM>>>(bqkv, nullptr);

    // 2) causal attention -> g_ao (fp16)
    attn_mma<<<dim3(SS/128, BHH), 256, ASMEM>>>();

    // 3) output projection -> out
    gemm_mma<1><<<dim3(DD/128, MTOT/128), 128, GSMEM>>>(bout, out);
}